// round 10
// baseline (speedup 1.0000x reference)
#include <cuda_runtime.h>
#include <cuda_bf16.h>
#include <cstdint>
#include <math.h>

#define BB 16
#define HH 768
#define WW 768
#define NPIX (HH*WW)
#define TOPK 100
#define NP 4
#define NPATCH (BB*NP)   // 64
#define PS 64            // patch size
#define CANDCAP 16384

// ---------------- scratch (static device globals) ----------------
__device__ float g_mask[BB*NPIX];
__device__ float g_tmp[BB*NPIX];
__device__ unsigned g_hist12[BB][4096];
__device__ unsigned g_T12[BB];
__device__ int g_candn[BB];
__device__ unsigned long long g_cand[BB][CANDCAP];
__device__ int g_py[NPATCH], g_px[NPATCH];
__device__ float g_patches[NPATCH*3*PS*PS];
__device__ unsigned g_a1pk[NPATCH*64*32*32];    // packed bf16 hi/lo
__device__ unsigned g_a2pk[NPATCH*128*16*16];
__device__ unsigned g_a3pk[NPATCH*256*8*8];
__device__ float g_act2[NPATCH*128*16*16];
__device__ float g_act3[NPATCH*256*8*8];
__device__ float g_act4[NPATCH*512*4*4];
__device__ unsigned g_wpk2[128*1024];
__device__ unsigned g_wpk3[256*2048];
__device__ unsigned g_wpk4[512*4096];
__device__ float g_part[4194304];
__device__ float g_bnscale[512], g_bnshift[512];

// ---------------- pack helper: fp32 -> (bf16hi<<16)|bf16lo ----------------
__device__ __forceinline__ unsigned packsplit(float v) {
    __nv_bfloat16 h = __float2bfloat16_rn(v);
    __nv_bfloat16 l = __float2bfloat16_rn(v - __bfloat162float(h));
    unsigned hu = *(unsigned short*)&h, lu = *(unsigned short*)&l;
    return (hu << 16) | lu;
}

// ---------------- detector fused into 15-tap horizontal pool ---------------
__global__ void hpool_det_kernel(const float* __restrict__ src) {
    if (blockIdx.y == 0 && blockIdx.x < 64) {
        int base = blockIdx.x * 1024;
        for (int i = threadIdx.x; i < 1024; i += 256)
            ((unsigned*)g_hist12)[base + i] = 0u;
    }
    if (blockIdx.y == 0 && blockIdx.x == 100 && threadIdx.x < BB)
        g_candn[threadIdx.x] = 0;

    __shared__ float row[WW + 14];
    int y = blockIdx.x, b = blockIdx.y;
    const float* sb = src + ((size_t)b*3*HH + y)*WW;
    for (int i = threadIdx.x; i < WW + 14; i += blockDim.x) {
        int x = i - 7;
        float m = 0.f;
        if (x >= 0 && x < WW) {
            float r  = (sb[x]               + 1.f)*0.5f;
            float gg = (sb[(size_t)HH*WW + x]   + 1.f)*0.5f;
            float bl = (sb[(size_t)2*HH*WW + x] + 1.f)*0.5f;
            float br = 0.299f*r + 0.587f*gg + 0.114f*bl;
            float bm = 1.f/(1.f + expf(-20.f*(br - 0.65f)));
            float mx = fmaxf(r, fmaxf(gg, bl));
            float mn = fminf(r, fminf(gg, bl));
            float ls = 1.f/(1.f + expf(-20.f*(0.15f - (mx - mn))));
            m = bm*ls;
        }
        row[i] = m;
    }
    __syncthreads();
    float* op = g_tmp + ((size_t)b*HH + y)*WW;
    for (int x = threadIdx.x; x < WW; x += blockDim.x) {
        float s = 0.f;
        #pragma unroll
        for (int d = 0; d < 15; d++) s += row[x + d];
        op[x] = s;
    }
}

// ---------------- 15-tap vertical sum + /225 -> g_mask, + 12-bit hist -----
__global__ void vpool_kernel() {
    __shared__ float tile[78][32];
    __shared__ unsigned shist[4096];
    int c0 = blockIdx.x*32, r0 = blockIdx.y*64, b = blockIdx.z;
    for (int i = threadIdx.x; i < 4096; i += blockDim.x) shist[i] = 0u;
    const float* ip = g_tmp + (size_t)b*NPIX;
    for (int i = threadIdx.x; i < 78*32; i += blockDim.x) {
        int r = i >> 5, c = i & 31;
        int y = r0 + r - 7;
        tile[r][c] = (y >= 0 && y < HH) ? ip[(size_t)y*WW + c0 + c] : 0.f;
    }
    __syncthreads();
    float* op = g_mask + (size_t)b*NPIX;
    int c = threadIdx.x & 31;
    for (int rr = threadIdx.x >> 5; rr < 64; rr += blockDim.x >> 5) {
        float s = 0.f;
        #pragma unroll
        for (int d = 0; d < 15; d++) s += tile[rr + d][c];
        float v = s / 225.0f;
        op[(size_t)(r0 + rr)*WW + c0 + c] = v;
        atomicAdd(&shist[__float_as_uint(v) >> 20], 1u);
    }
    __syncthreads();
    for (int i = threadIdx.x; i < 4096; i += blockDim.x) {
        unsigned cc = shist[i];
        if (cc) atomicAdd(&g_hist12[b][i], cc);
    }
}

// ---------------- resolve 12-bit threshold ----------------
__global__ void topk_resolve_kernel() {
    int b = blockIdx.x, t = threadIdx.x;   // 256 threads
    __shared__ unsigned csum[257];
    __shared__ int s_c;
    unsigned s = 0;
    #pragma unroll
    for (int j = 0; j < 16; j++) s += g_hist12[b][t*16 + j];
    csum[t] = s;
    if (t == 0) csum[256] = 0;
    __syncthreads();
    for (int off = 1; off < 256; off <<= 1) {
        unsigned v = csum[t] + ((t + off < 256) ? csum[t + off] : 0u);
        __syncthreads();
        csum[t] = v;
        __syncthreads();
    }
    if (csum[t] >= TOPK && (t == 255 || csum[t + 1] < TOPK)) s_c = t;
    __syncthreads();
    if (t == 0) {
        int cch = s_c;
        unsigned running = (cch == 255) ? 0u : csum[cch + 1];
        unsigned T = (unsigned)(cch*16);
        for (int bin = cch*16 + 15; bin >= cch*16; bin--) {
            running += g_hist12[b][bin];
            if (running >= TOPK) { T = (unsigned)bin; break; }
        }
        g_T12[b] = T;
    }
}

// ---------------- collect candidates (one full scan, grid-wide) ----------
__global__ void topk_collect_kernel() {
    int b = blockIdx.y;
    unsigned T = g_T12[b];
    const float4* wp4 = (const float4*)(g_mask + (size_t)b*NPIX);
    for (int i = blockIdx.x*blockDim.x + threadIdx.x; i < NPIX/4; i += gridDim.x*blockDim.x) {
        float4 v = wp4[i];
        unsigned kk[4] = {__float_as_uint(v.x), __float_as_uint(v.y),
                          __float_as_uint(v.z), __float_as_uint(v.w)};
        #pragma unroll
        for (int j = 0; j < 4; j++) {
            if ((kk[j] >> 20) >= T) {
                int p = atomicAdd(&g_candn[b], 1);
                if (p < CANDCAP)
                    g_cand[b][p] = ((unsigned long long)kk[j] << 32)
                                 | (unsigned)(0xFFFFFFFFu - (unsigned)(4*i + j));
            }
        }
    }
}

// ---------------- exact top-100 by rank + coords ----------------
__global__ __launch_bounds__(1024) void topk_final_kernel(const int* __restrict__ rand_sel) {
    int b = blockIdx.x, tid = threadIdx.x;
    __shared__ unsigned long long ch[2048];
    __shared__ int stop[TOPK];
    int n = min(g_candn[b], CANDCAP);
    unsigned long long vi[16]; int ri[16]; int nc = 0;
    for (int i = tid; i < n; i += 1024) {
        if (nc < 16) { vi[nc] = g_cand[b][i]; ri[nc] = 0; nc++; }
    }
    for (int base = 0; base < n; base += 2048) {
        int len = min(2048, n - base);
        for (int j = tid; j < len; j += 1024) ch[j] = g_cand[b][base + j];
        __syncthreads();
        for (int cnd = 0; cnd < nc; cnd++) {
            unsigned long long v = vi[cnd]; int r = 0;
            for (int j = 0; j < len; j++) r += (ch[j] > v) ? 1 : 0;
            ri[cnd] += r;
        }
        __syncthreads();
    }
    for (int cnd = 0; cnd < nc; cnd++)
        if (ri[cnd] < TOPK)
            stop[ri[cnd]] = (int)(0xFFFFFFFFu - (unsigned)(vi[cnd] & 0xFFFFFFFFu));
    __syncthreads();
    if (tid < NP) {
        int r = rand_sel[b*NP + tid];
        int sel = stop[r];
        int y = sel / WW - PS/2; y = max(0, min(y, HH - PS));
        int x = sel % WW - PS/2; x = max(0, min(x, WW - PS));
        g_py[b*NP + tid] = y; g_px[b*NP + tid] = x;
    }
}

// ---------------- patch gather ----------------
__global__ void gather_kernel(const float* __restrict__ pred) {
    int idx = blockIdx.x*blockDim.x + threadIdx.x;
    const int total = NPATCH*3*PS*PS;
    if (idx >= total) return;
    int j = idx & 63; int t = idx >> 6;
    int i = t & 63;   t >>= 6;
    int c = t % 3;    int p = t / 3;
    int b = p >> 2;
    g_patches[idx] = pred[(((size_t)b*3 + c)*HH + g_py[p] + i)*WW + g_px[p] + j];
}

// ---------------- weight pre-split: 3 weight tensors -> packed planes ----
__global__ void wsplit_all_kernel(const float* __restrict__ w2,
                                  const float* __restrict__ w3,
                                  const float* __restrict__ w4) {
    int which = blockIdx.y;
    const float* w = (which == 0) ? w2 : (which == 1) ? w3 : w4;
    unsigned* o = (which == 0) ? g_wpk2 : (which == 1) ? g_wpk3 : g_wpk4;
    int n = (which == 0) ? 131072 : (which == 1) ? 524288 : 2097152;
    for (int i = blockIdx.x*blockDim.x + threadIdx.x; i < n; i += gridDim.x*blockDim.x)
        o[i] = packsplit(w[i]);
}

// ---------------- bn apply + lrelu + pack ----------------
__global__ void bnsplit_kernel(const float* __restrict__ x, unsigned* __restrict__ o,
                               int total, int log_s, int cmask) {
    for (int idx = blockIdx.x*blockDim.x + threadIdx.x; idx < total; idx += gridDim.x*blockDim.x) {
        int c = (idx >> log_s) & cmask;
        float v = x[idx]*g_bnscale[c] + g_bnshift[c];
        v = v > 0.f ? v : 0.2f*v;
        o[idx] = packsplit(v);
    }
}

// ---------------- conv1: implicit GEMM 64x64 FFMA, K=48, packs output ----
__global__ __launch_bounds__(256) void conv1_kernel(
        const float* __restrict__ in, const float* __restrict__ w,
        const float* __restrict__ bias, unsigned* __restrict__ out) {
    constexpr int IC = 3, LOG_OW = 5, OW = 32, OHW = OW*OW, IW = 64, IH = 64, K = 48;
    __shared__ __align__(16) float As[2][16][68];
    __shared__ __align__(16) float Bs[2][16][68];
    const int tid = threadIdx.x;
    const int m0  = blockIdx.x << 6;

    const int lm = tid >> 2;
    const int kq = (tid & 3) << 2;
    const int am   = m0 + lm;
    const int nimg = am >> (2*LOG_OW);
    const int arem = am & (OHW-1);
    const int ih0  = ((arem >> LOG_OW) << 1) - 1;
    const int iw0  = ((arem & (OW-1)) << 1) - 1;
    const float* ibase = in + (size_t)nimg*IC*IH*IW;

    const int boc = tid >> 2;
    const int bkq = (tid & 3) << 2;

    const int tm = (tid >> 4) << 2;
    const int tn = (tid & 15) << 2;

    float acc[4][4] = {};
    float pa[4]; float4 pbv;

    auto loadA = [&](int kc) {
        int k  = kc + kq;
        int ic = k >> 4;
        int ih = ih0 + ((k >> 2) & 3);
        const float* rp = ibase + ((size_t)ic*IH + ih)*IW;
        bool rowok = (unsigned)ih < (unsigned)IH;
        #pragma unroll
        for (int j = 0; j < 4; j++) {
            int iw = iw0 + j;
            pa[j] = (rowok && (unsigned)iw < (unsigned)IW) ? __ldg(rp + iw) : 0.f;
        }
    };
    auto loadB = [&](int kc) {
        pbv = *(const float4*)&w[(size_t)boc*K + kc + bkq];
    };
    auto stsA = [&](int buf) {
        #pragma unroll
        for (int j = 0; j < 4; j++) As[buf][kq+j][lm] = pa[j];
    };
    auto stsB = [&](int buf) {
        Bs[buf][bkq+0][boc] = pbv.x; Bs[buf][bkq+1][boc] = pbv.y;
        Bs[buf][bkq+2][boc] = pbv.z; Bs[buf][bkq+3][boc] = pbv.w;
    };

    loadA(0); loadB(0); stsA(0); stsB(0); __syncthreads();
    const int nch = K >> 4;
    for (int ch = 0; ch < nch; ch++) {
        int cur = ch & 1;
        if (ch + 1 < nch) { loadA((ch+1) << 4); loadB((ch+1) << 4); }
        #pragma unroll
        for (int k = 0; k < 16; k++) {
            float4 a = *(const float4*)&As[cur][k][tm];
            float4 b = *(const float4*)&Bs[cur][k][tn];
            acc[0][0] += a.x*b.x; acc[0][1] += a.x*b.y; acc[0][2] += a.x*b.z; acc[0][3] += a.x*b.w;
            acc[1][0] += a.y*b.x; acc[1][1] += a.y*b.y; acc[1][2] += a.y*b.z; acc[1][3] += a.y*b.w;
            acc[2][0] += a.z*b.x; acc[2][1] += a.z*b.y; acc[2][2] += a.z*b.z; acc[2][3] += a.z*b.w;
            acc[3][0] += a.w*b.x; acc[3][1] += a.w*b.y; acc[3][2] += a.w*b.z; acc[3][3] += a.w*b.w;
        }
        if (ch + 1 < nch) { stsA(cur ^ 1); stsB(cur ^ 1); __syncthreads(); }
    }

    const float4 bv = *(const float4*)&bias[tn];
    float b4[4] = {bv.x, bv.y, bv.z, bv.w};
    #pragma unroll
    for (int i = 0; i < 4; i++) {
        int m    = m0 + tm + i;
        int ni   = m >> (2*LOG_OW);
        int rem  = m & (OHW-1);
        unsigned* op = out + ((size_t)ni*64 + tn)*OHW + rem;
        #pragma unroll
        for (int j = 0; j < 4; j++) {
            float v = acc[i][j] + b4[j];
            v = v > 0.f ? v : 0.2f*v;
            op[(size_t)j*OHW] = packsplit(v);
        }
    }
}

// ---------------- mma helper ----------------
__device__ __forceinline__ void mma_bf16(float* c, const unsigned* a, const unsigned* b) {
    asm volatile(
        "mma.sync.aligned.m16n8k16.row.col.f32.bf16.bf16.f32 "
        "{%0,%1,%2,%3}, {%4,%5,%6,%7}, {%8,%9}, {%0,%1,%2,%3};"
        : "+f"(c[0]), "+f"(c[1]), "+f"(c[2]), "+f"(c[3])
        : "r"(a[0]), "r"(a[1]), "r"(a[2]), "r"(a[3]), "r"(b[0]), "r"(b[1]));
}

// ---------------- conv2-4: packed bf16-split MMA, BM=64 BN=128 BK=32 ------
// Inputs pre-packed (hi<<16)|lo u32. No conversions in hot loop.
#define MSTR 40
#define SMEM_SZ (2*64*MSTR*2*2 + 2*128*MSTR*2*2)   // 61440
template<int IC, int LOG_OW>
__global__ __launch_bounds__(256, 2) void conv_mma_kernel(
        const unsigned* __restrict__ Apk, const unsigned* __restrict__ Wpk,
        float* __restrict__ part, int K, int Kchunk) {
    constexpr int OW = 1 << LOG_OW, OHW = OW*OW, IW = 2*OW, IH = IW;
    extern __shared__ __align__(16) char dsm[];
    uint16_t* Ah = (uint16_t*)dsm;            // [2][64][MSTR]
    uint16_t* Al = Ah + 2*64*MSTR;
    uint16_t* Bh = Al + 2*64*MSTR;            // [2][128][MSTR]
    uint16_t* Bl = Bh + 2*128*MSTR;

    const int tid = threadIdx.x;
    const int m0  = blockIdx.x << 6;
    const int n0  = blockIdx.y << 7;
    const int NN  = gridDim.y << 7;
    const int MM  = gridDim.x << 6;
    const int k0  = blockIdx.z * Kchunk;
    float* pout = part + (size_t)blockIdx.z * MM * NN;

    // A mapping: row lm (0..63), k-range kq8..kq8+7
    const int lm  = tid >> 2;
    const int kq8 = (tid & 3) << 3;
    const int am   = m0 + lm;
    const int nimg = am >> (2*LOG_OW);
    const int arem = am & (OHW-1);
    const int ih0  = ((arem >> LOG_OW) << 1) - 1;
    const int iw0  = ((arem & (OW-1)) << 1) - 1;
    const unsigned* ibase = Apk + (size_t)nimg*IC*IH*IW;

    // B mapping: row brow (0..127), k-range bk16..bk16+15
    const int brow = tid >> 1;
    const int bk16 = (tid & 1) << 4;
    const unsigned* wrow = Wpk + (size_t)(n0 + brow)*K;

    // warp layout: 2(m) x 4(n), warp tile 32x32
    const int wid  = tid >> 5, lane = tid & 31;
    const int wm   = (wid >> 2) << 5;
    const int wn   = (wid & 3) << 5;
    const int g    = lane >> 2;
    const int q    = lane & 3;

    float acc[2][4][4];
    #pragma unroll
    for (int i = 0; i < 2; i++)
        #pragma unroll
        for (int j = 0; j < 4; j++)
            #pragma unroll
            for (int e = 0; e < 4; e++) acc[i][j][e] = 0.f;

    unsigned pw[8]; uint4 wv[4];

    auto loadA = [&](int kc) {
        int kbase = kc + kq8;
        int ic = kbase >> 4;
        #pragma unroll
        for (int grp = 0; grp < 2; grp++) {
            int k  = kbase + grp*4;
            int ih = ih0 + ((k >> 2) & 3);
            const unsigned* rp = ibase + ((size_t)ic*IH + ih)*IW;
            bool rowok = (unsigned)ih < (unsigned)IH;
            #pragma unroll
            for (int j = 0; j < 4; j++) {
                int iw = iw0 + j;
                pw[grp*4 + j] = (rowok && (unsigned)iw < (unsigned)IW) ? __ldg(rp + iw) : 0u;
            }
        }
    };
    auto loadB = [&](int kc) {
        #pragma unroll
        for (int j = 0; j < 4; j++)
            wv[j] = *(const uint4*)(wrow + kc + bk16 + 4*j);
    };
    auto stsA = [&](int buf) {
        unsigned h[4], l[4];
        #pragma unroll
        for (int p = 0; p < 4; p++) {
            h[p] = __byte_perm(pw[2*p], pw[2*p+1], 0x7632);
            l[p] = __byte_perm(pw[2*p], pw[2*p+1], 0x5410);
        }
        *(uint4*)&Ah[(buf*64 + lm)*MSTR + kq8] = make_uint4(h[0], h[1], h[2], h[3]);
        *(uint4*)&Al[(buf*64 + lm)*MSTR + kq8] = make_uint4(l[0], l[1], l[2], l[3]);
    };
    auto stsB = [&](int buf) {
        const unsigned* wp = (const unsigned*)wv;
        unsigned h[8], l[8];
        #pragma unroll
        for (int p = 0; p < 8; p++) {
            h[p] = __byte_perm(wp[2*p], wp[2*p+1], 0x7632);
            l[p] = __byte_perm(wp[2*p], wp[2*p+1], 0x5410);
        }
        int base = (buf*128 + brow)*MSTR + bk16;
        *(uint4*)&Bh[base]     = make_uint4(h[0], h[1], h[2], h[3]);
        *(uint4*)&Bh[base + 8] = make_uint4(h[4], h[5], h[6], h[7]);
        *(uint4*)&Bl[base]     = make_uint4(l[0], l[1], l[2], l[3]);
        *(uint4*)&Bl[base + 8] = make_uint4(l[4], l[5], l[6], l[7]);
    };

    loadA(k0); loadB(k0); stsA(0); stsB(0); __syncthreads();
    const int nch = Kchunk >> 5;
    for (int ch = 0; ch < nch; ch++) {
        int cur = ch & 1;
        if (ch + 1 < nch) { loadA(k0 + ((ch+1) << 5)); loadB(k0 + ((ch+1) << 5)); }
        #pragma unroll
        for (int step = 0; step < 2; step++) {
            const int ko = step*16 + q*2;
            unsigned ah[2][4], al[2][4], bh[4][2], bl[4][2];
            #pragma unroll
            for (int mf = 0; mf < 2; mf++) {
                int r = (cur*64 + wm + mf*16 + g)*MSTR;
                ah[mf][0] = *(const unsigned*)&Ah[r + ko];
                ah[mf][1] = *(const unsigned*)&Ah[r + 8*MSTR + ko];
                ah[mf][2] = *(const unsigned*)&Ah[r + ko + 8];
                ah[mf][3] = *(const unsigned*)&Ah[r + 8*MSTR + ko + 8];
                al[mf][0] = *(const unsigned*)&Al[r + ko];
                al[mf][1] = *(const unsigned*)&Al[r + 8*MSTR + ko];
                al[mf][2] = *(const unsigned*)&Al[r + ko + 8];
                al[mf][3] = *(const unsigned*)&Al[r + 8*MSTR + ko + 8];
            }
            #pragma unroll
            for (int nf = 0; nf < 4; nf++) {
                int rb = (cur*128 + wn + nf*8 + g)*MSTR;
                bh[nf][0] = *(const unsigned*)&Bh[rb + ko];
                bh[nf][1] = *(const unsigned*)&Bh[rb + ko + 8];
                bl[nf][0] = *(const unsigned*)&Bl[rb + ko];
                bl[nf][1] = *(const unsigned*)&Bl[rb + ko + 8];
            }
            #pragma unroll
            for (int mf = 0; mf < 2; mf++)
                #pragma unroll
                for (int nf = 0; nf < 4; nf++) {
                    mma_bf16(acc[mf][nf], ah[mf], bh[nf]);
                    mma_bf16(acc[mf][nf], ah[mf], bl[nf]);
                    mma_bf16(acc[mf][nf], al[mf], bh[nf]);
                }
        }
        if (ch + 1 < nch) { stsA(cur ^ 1); stsB(cur ^ 1); __syncthreads(); }
    }

    #pragma unroll
    for (int mf = 0; mf < 2; mf++) {
        #pragma unroll
        for (int nf = 0; nf < 4; nf++) {
            int r0 = m0 + wm + mf*16 + g;
            int r1 = r0 + 8;
            int c0 = n0 + wn + nf*8 + q*2;
            *(float2*)(pout + (size_t)r0*NN + c0) = make_float2(acc[mf][nf][0], acc[mf][nf][1]);
            *(float2*)(pout + (size_t)r1*NN + c0) = make_float2(acc[mf][nf][2], acc[mf][nf][3]);
        }
    }
}

// ---------------- split-K reduce + bias -> NCHW ----------------
__global__ void redk_kernel(const float* __restrict__ part, const float* __restrict__ bias,
                            float* __restrict__ out, int MN, int log_nn, int KS, int log_ohw) {
    int NNm = (1 << log_nn) - 1;
    int OHWm = (1 << log_ohw) - 1;
    for (int idx = blockIdx.x*blockDim.x + threadIdx.x; idx < MN; idx += gridDim.x*blockDim.x) {
        int m = idx >> log_nn, n = idx & NNm;
        float s = 0.f;
        for (int z = 0; z < KS; z++) s += part[(size_t)z*MN + idx];
        s += bias[n];
        int ni = m >> log_ohw, rem = m & OHWm;
        out[((((size_t)ni << log_nn) + n) << log_ohw) + rem] = s;
    }
}

// ---------------- batchnorm stats (double accum) ----------------
__global__ void bn_reduce_kernel(const float* __restrict__ x, const float* __restrict__ g,
                                 const float* __restrict__ be, int N, int C, int S) {
    int c = blockIdx.x;
    double s = 0.0, s2 = 0.0;
    int M = N*S;
    for (int j = threadIdx.x; j < M; j += blockDim.x) {
        int n = j / S, sp = j % S;
        float v = x[((size_t)n*C + c)*S + sp];
        s += (double)v; s2 += (double)v*(double)v;
    }
    __shared__ double sh[256], sh2[256];
    sh[threadIdx.x] = s; sh2[threadIdx.x] = s2; __syncthreads();
    for (int st = 128; st > 0; st >>= 1) {
        if (threadIdx.x < st) { sh[threadIdx.x] += sh[threadIdx.x+st]; sh2[threadIdx.x] += sh2[threadIdx.x+st]; }
        __syncthreads();
    }
    if (threadIdx.x == 0) {
        double mean = sh[0] / M;
        double var  = sh2[0] / M - mean*mean;
        double isd  = 1.0 / sqrt(var + 1e-5);
        float sc = (float)((double)g[c] * isd);
        g_bnscale[c] = sc;
        g_bnshift[c] = be[c] - (float)(mean * (double)sc);
    }
}

// ---------------- head: bn4+lrelu+conv5 dot+softplus+mean ----------------
__global__ void head_kernel(const float* __restrict__ a4, const float* __restrict__ w5,
                            const float* __restrict__ b5, float* __restrict__ out) {
    int tid = threadIdx.x;            // 512
    int lane = tid & 31, warp = tid >> 5;   // 16 warps
    __shared__ float slog[64];
    for (int p = warp; p < NPATCH; p += 16) {
        const float* ap = a4 + (size_t)p*8192;
        float s = 0.f;
        for (int i = lane; i < 8192; i += 32) {
            int c = i >> 4;
            float v = ap[i]*g_bnscale[c] + g_bnshift[c];
            v = v > 0.f ? v : 0.2f*v;
            s += v * w5[i];
        }
        #pragma unroll
        for (int d = 16; d > 0; d >>= 1) s += __shfl_xor_sync(0xFFFFFFFFu, s, d);
        if (lane == 0) slog[p] = s + b5[0];
    }
    __syncthreads();
    if (tid < 64) {
        float x = -slog[tid];
        slog[tid] = fmaxf(x, 0.f) + log1pf(expf(-fabsf(x)));
    }
    __syncthreads();
    if (tid < 32) {
        float v = slog[tid] + slog[tid + 32];
        #pragma unroll
        for (int d = 16; d > 0; d >>= 1) v += __shfl_xor_sync(0xFFFFFFFFu, v, d);
        if (tid == 0) out[0] = v / 64.f;
    }
}

// ---------------- launcher ----------------
extern "C" void kernel_launch(void* const* d_in, const int* in_sizes, int n_in,
                              void* d_out, int out_size) {
    const float* pred     = (const float*)d_in[0];
    const float* source   = (const float*)d_in[1];
    const int*   rand_sel = (const int*)d_in[2];
    const float* w1 = (const float*)d_in[3];  const float* b1 = (const float*)d_in[4];
    const float* w2 = (const float*)d_in[5];  const float* b2 = (const float*)d_in[6];
    const float* g2 = (const float*)d_in[7];  const float* be2= (const float*)d_in[8];
    const float* w3 = (const float*)d_in[9];  const float* b3 = (const float*)d_in[10];
    const float* g3 = (const float*)d_in[11]; const float* be3= (const float*)d_in[12];
    const float* w4 = (const float*)d_in[13]; const float* b4 = (const float*)d_in[14];
    const float* g4 = (const float*)d_in[15]; const float* be4= (const float*)d_in[16];
    const float* w5 = (const float*)d_in[17]; const float* b5 = (const float*)d_in[18];
    float* out = (float*)d_out;

    float *patches, *a2, *a3, *a4, *part;
    unsigned *a1pk, *a2pk, *a3pk, *wpk2, *wpk3, *wpk4;
    cudaGetSymbolAddress((void**)&patches, g_patches);
    cudaGetSymbolAddress((void**)&a1pk, g_a1pk);
    cudaGetSymbolAddress((void**)&a2pk, g_a2pk);
    cudaGetSymbolAddress((void**)&a3pk, g_a3pk);
    cudaGetSymbolAddress((void**)&a2, g_act2);
    cudaGetSymbolAddress((void**)&a3, g_act3);
    cudaGetSymbolAddress((void**)&a4, g_act4);
    cudaGetSymbolAddress((void**)&wpk2, g_wpk2);
    cudaGetSymbolAddress((void**)&wpk3, g_wpk3);
    cudaGetSymbolAddress((void**)&wpk4, g_wpk4);
    cudaGetSymbolAddress((void**)&part, g_part);

    cudaFuncSetAttribute(conv_mma_kernel<64, 4>,
                         cudaFuncAttributeMaxDynamicSharedMemorySize, SMEM_SZ);
    cudaFuncSetAttribute(conv_mma_kernel<128, 3>,
                         cudaFuncAttributeMaxDynamicSharedMemorySize, SMEM_SZ);
    cudaFuncSetAttribute(conv_mma_kernel<256, 2>,
                         cudaFuncAttributeMaxDynamicSharedMemorySize, SMEM_SZ);

    // weight pre-split (independent of data path)
    wsplit_all_kernel<<<dim3(512, 3), 256>>>(w2, w3, w4);
    // detector + pools (hist fused into vpool)
    hpool_det_kernel<<<dim3(HH, BB), 256>>>(source);
    vpool_kernel<<<dim3(WW/32, HH/64, BB), 256>>>();
    // topk: resolve threshold, collect candidates, exact rank
    topk_resolve_kernel<<<BB, 256>>>();
    topk_collect_kernel<<<dim3(48, BB), 256>>>();
    topk_final_kernel<<<BB, 1024>>>(rand_sel);
    // patch gather
    gather_kernel<<<(NPATCH*3*PS*PS + 255)/256, 256>>>(pred);
    // conv1 (FFMA implicit GEMM, bias+lrelu fused, packs bf16 hi/lo output)
    conv1_kernel<<<1024, 256>>>(patches, w1, b1, a1pk);
    // conv2: M=16384, N=128, K=1024, split-K=2
    conv_mma_kernel<64, 4><<<dim3(256, 1, 2), 256, SMEM_SZ>>>(a1pk, wpk2, part, 1024, 512);
    redk_kernel<<<2048, 256>>>(part, b2, a2, 16384*128, 7, 2, 8);
    bn_reduce_kernel<<<128, 256>>>(a2, g2, be2, NPATCH, 128, 16*16);
    bnsplit_kernel<<<1024, 256>>>(a2, a2pk, NPATCH*128*16*16, 8, 127);
    // conv3: M=4096, N=256, K=2048, split-K=4
    conv_mma_kernel<128, 3><<<dim3(64, 2, 4), 256, SMEM_SZ>>>(a2pk, wpk3, part, 2048, 512);
    redk_kernel<<<1024, 256>>>(part, b3, a3, 4096*256, 8, 4, 6);
    bn_reduce_kernel<<<256, 256>>>(a3, g3, be3, NPATCH, 256, 8*8);
    bnsplit_kernel<<<512, 256>>>(a3, a3pk, NPATCH*256*8*8, 6, 255);
    // conv4: M=1024, N=512, K=4096, split-K=8
    conv_mma_kernel<256, 2><<<dim3(16, 4, 8), 256, SMEM_SZ>>>(a3pk, wpk4, part, 4096, 512);
    redk_kernel<<<512, 256>>>(part, b4, a4, 1024*512, 9, 8, 4);
    bn_reduce_kernel<<<512, 256>>>(a4, g4, be4, NPATCH, 512, 4*4);
    // head: bn4+lrelu+conv5+softplus+mean
    head_kernel<<<1, 512>>>(a4, w5, b5, out);
}

// round 12
// speedup vs baseline: 1.1573x; 1.1573x over previous
#include <cuda_runtime.h>
#include <cuda_fp16.h>
#include <cstdint>
#include <math.h>

#define BB 16
#define HH 768
#define WW 768
#define NPIX (HH*WW)
#define TOPK 100
#define NP 4
#define NPATCH (BB*NP)   // 64
#define PS 64            // patch size
#define CANDCAP 16384

// ---------------- scratch (static device globals) ----------------
__device__ float g_mask[BB*NPIX];
__device__ float g_tmp[BB*NPIX];
__device__ unsigned g_hist12[BB][4096];
__device__ unsigned g_T12[BB];
__device__ int g_candn[BB];
__device__ unsigned long long g_cand[BB][CANDCAP];
__device__ int g_py[NPATCH], g_px[NPATCH];
__device__ float g_patches[NPATCH*3*PS*PS];
__device__ __half g_a1h[NPATCH*64*32*32];
__device__ __half g_a2h[NPATCH*128*16*16];
__device__ __half g_a3h[NPATCH*256*8*8];
__device__ float g_act2[NPATCH*128*16*16];
__device__ float g_act3[NPATCH*256*8*8];
__device__ float g_act4[NPATCH*512*4*4];
__device__ __half g_wh2[128*1024];
__device__ __half g_wh3[256*2048];
__device__ __half g_wh4[512*4096];
__device__ float g_part[4194304];
__device__ float g_bnscale[512], g_bnshift[512];

// ---------------- detector fused into 15-tap horizontal pool ---------------
__global__ void hpool_det_kernel(const float* __restrict__ src) {
    if (blockIdx.y == 0 && blockIdx.x < 64) {
        int base = blockIdx.x * 1024;
        for (int i = threadIdx.x; i < 1024; i += 256)
            ((unsigned*)g_hist12)[base + i] = 0u;
    }
    if (blockIdx.y == 0 && blockIdx.x == 100 && threadIdx.x < BB)
        g_candn[threadIdx.x] = 0;

    __shared__ float row[WW + 14];
    int y = blockIdx.x, b = blockIdx.y;
    const float* sb = src + ((size_t)b*3*HH + y)*WW;
    for (int i = threadIdx.x; i < WW + 14; i += blockDim.x) {
        int x = i - 7;
        float m = 0.f;
        if (x >= 0 && x < WW) {
            float r  = (sb[x]               + 1.f)*0.5f;
            float gg = (sb[(size_t)HH*WW + x]   + 1.f)*0.5f;
            float bl = (sb[(size_t)2*HH*WW + x] + 1.f)*0.5f;
            float br = 0.299f*r + 0.587f*gg + 0.114f*bl;
            float bm = 1.f/(1.f + expf(-20.f*(br - 0.65f)));
            float mx = fmaxf(r, fmaxf(gg, bl));
            float mn = fminf(r, fminf(gg, bl));
            float ls = 1.f/(1.f + expf(-20.f*(0.15f - (mx - mn))));
            m = bm*ls;
        }
        row[i] = m;
    }
    __syncthreads();
    float* op = g_tmp + ((size_t)b*HH + y)*WW;
    for (int x = threadIdx.x; x < WW; x += blockDim.x) {
        float s = 0.f;
        #pragma unroll
        for (int d = 0; d < 15; d++) s += row[x + d];
        op[x] = s;
    }
}

// ---------------- 15-tap vertical sum + /225 -> g_mask, + 12-bit hist -----
__global__ void vpool_kernel() {
    __shared__ float tile[78][32];
    __shared__ unsigned shist[4096];
    int c0 = blockIdx.x*32, r0 = blockIdx.y*64, b = blockIdx.z;
    for (int i = threadIdx.x; i < 4096; i += blockDim.x) shist[i] = 0u;
    const float* ip = g_tmp + (size_t)b*NPIX;
    for (int i = threadIdx.x; i < 78*32; i += blockDim.x) {
        int r = i >> 5, c = i & 31;
        int y = r0 + r - 7;
        tile[r][c] = (y >= 0 && y < HH) ? ip[(size_t)y*WW + c0 + c] : 0.f;
    }
    __syncthreads();
    float* op = g_mask + (size_t)b*NPIX;
    int c = threadIdx.x & 31;
    for (int rr = threadIdx.x >> 5; rr < 64; rr += blockDim.x >> 5) {
        float s = 0.f;
        #pragma unroll
        for (int d = 0; d < 15; d++) s += tile[rr + d][c];
        float v = s / 225.0f;
        op[(size_t)(r0 + rr)*WW + c0 + c] = v;
        atomicAdd(&shist[__float_as_uint(v) >> 20], 1u);
    }
    __syncthreads();
    for (int i = threadIdx.x; i < 4096; i += blockDim.x) {
        unsigned cc = shist[i];
        if (cc) atomicAdd(&g_hist12[b][i], cc);
    }
}

// ---------------- resolve 12-bit threshold ----------------
__global__ void topk_resolve_kernel() {
    int b = blockIdx.x, t = threadIdx.x;   // 256 threads
    __shared__ unsigned csum[257];
    __shared__ int s_c;
    unsigned s = 0;
    #pragma unroll
    for (int j = 0; j < 16; j++) s += g_hist12[b][t*16 + j];
    csum[t] = s;
    if (t == 0) csum[256] = 0;
    __syncthreads();
    for (int off = 1; off < 256; off <<= 1) {
        unsigned v = csum[t] + ((t + off < 256) ? csum[t + off] : 0u);
        __syncthreads();
        csum[t] = v;
        __syncthreads();
    }
    if (csum[t] >= TOPK && (t == 255 || csum[t + 1] < TOPK)) s_c = t;
    __syncthreads();
    if (t == 0) {
        int cch = s_c;
        unsigned running = (cch == 255) ? 0u : csum[cch + 1];
        unsigned T = (unsigned)(cch*16);
        for (int bin = cch*16 + 15; bin >= cch*16; bin--) {
            running += g_hist12[b][bin];
            if (running >= TOPK) { T = (unsigned)bin; break; }
        }
        g_T12[b] = T;
    }
}

// ---------------- collect candidates (one full scan, grid-wide) ----------
__global__ void topk_collect_kernel() {
    int b = blockIdx.y;
    unsigned T = g_T12[b];
    const float4* wp4 = (const float4*)(g_mask + (size_t)b*NPIX);
    for (int i = blockIdx.x*blockDim.x + threadIdx.x; i < NPIX/4; i += gridDim.x*blockDim.x) {
        float4 v = wp4[i];
        unsigned kk[4] = {__float_as_uint(v.x), __float_as_uint(v.y),
                          __float_as_uint(v.z), __float_as_uint(v.w)};
        #pragma unroll
        for (int j = 0; j < 4; j++) {
            if ((kk[j] >> 20) >= T) {
                int p = atomicAdd(&g_candn[b], 1);
                if (p < CANDCAP)
                    g_cand[b][p] = ((unsigned long long)kk[j] << 32)
                                 | (unsigned)(0xFFFFFFFFu - (unsigned)(4*i + j));
            }
        }
    }
}

// ---------------- exact top-100 by rank + coords ----------------
__global__ __launch_bounds__(1024) void topk_final_kernel(const int* __restrict__ rand_sel) {
    int b = blockIdx.x, tid = threadIdx.x;
    __shared__ unsigned long long ch[2048];
    __shared__ int stop[TOPK];
    int n = min(g_candn[b], CANDCAP);
    unsigned long long vi[16]; int ri[16]; int nc = 0;
    for (int i = tid; i < n; i += 1024) {
        if (nc < 16) { vi[nc] = g_cand[b][i]; ri[nc] = 0; nc++; }
    }
    for (int base = 0; base < n; base += 2048) {
        int len = min(2048, n - base);
        for (int j = tid; j < len; j += 1024) ch[j] = g_cand[b][base + j];
        __syncthreads();
        for (int cnd = 0; cnd < nc; cnd++) {
            unsigned long long v = vi[cnd]; int r = 0;
            for (int j = 0; j < len; j++) r += (ch[j] > v) ? 1 : 0;
            ri[cnd] += r;
        }
        __syncthreads();
    }
    for (int cnd = 0; cnd < nc; cnd++)
        if (ri[cnd] < TOPK)
            stop[ri[cnd]] = (int)(0xFFFFFFFFu - (unsigned)(vi[cnd] & 0xFFFFFFFFu));
    __syncthreads();
    if (tid < NP) {
        int r = rand_sel[b*NP + tid];
        int sel = stop[r];
        int y = sel / WW - PS/2; y = max(0, min(y, HH - PS));
        int x = sel % WW - PS/2; x = max(0, min(x, WW - PS));
        g_py[b*NP + tid] = y; g_px[b*NP + tid] = x;
    }
}

// ---------------- patch gather ----------------
__global__ void gather_kernel(const float* __restrict__ pred) {
    int idx = blockIdx.x*blockDim.x + threadIdx.x;
    const int total = NPATCH*3*PS*PS;
    if (idx >= total) return;
    int j = idx & 63; int t = idx >> 6;
    int i = t & 63;   t >>= 6;
    int c = t % 3;    int p = t / 3;
    int b = p >> 2;
    g_patches[idx] = pred[(((size_t)b*3 + c)*HH + g_py[p] + i)*WW + g_px[p] + j];
}

// ---------------- weight convert: fp32 -> fp16 ----------------
__global__ void wsplit_all_kernel(const float* __restrict__ w2,
                                  const float* __restrict__ w3,
                                  const float* __restrict__ w4) {
    int which = blockIdx.y;
    const float* w = (which == 0) ? w2 : (which == 1) ? w3 : w4;
    __half* o = (which == 0) ? g_wh2 : (which == 1) ? g_wh3 : g_wh4;
    int n = (which == 0) ? 131072 : (which == 1) ? 524288 : 2097152;
    for (int i = blockIdx.x*blockDim.x + threadIdx.x; i < n; i += gridDim.x*blockDim.x)
        o[i] = __float2half_rn(w[i]);
}

// ---------------- bn apply + lrelu + fp16 convert ----------------
__global__ void bnsplit_kernel(const float* __restrict__ x, __half* __restrict__ o,
                               int total, int log_s, int cmask) {
    for (int idx = blockIdx.x*blockDim.x + threadIdx.x; idx < total; idx += gridDim.x*blockDim.x) {
        int c = (idx >> log_s) & cmask;
        float v = x[idx]*g_bnscale[c] + g_bnshift[c];
        v = v > 0.f ? v : 0.2f*v;
        o[idx] = __float2half_rn(v);
    }
}

// ---------------- conv1: implicit GEMM 64x64 FFMA, K=48, fp16 output ----
__global__ __launch_bounds__(256) void conv1_kernel(
        const float* __restrict__ in, const float* __restrict__ w,
        const float* __restrict__ bias, __half* __restrict__ out) {
    constexpr int IC = 3, LOG_OW = 5, OW = 32, OHW = OW*OW, IW = 64, IH = 64, K = 48;
    __shared__ __align__(16) float As[2][16][68];
    __shared__ __align__(16) float Bs[2][16][68];
    const int tid = threadIdx.x;
    const int m0  = blockIdx.x << 6;

    const int lm = tid >> 2;
    const int kq = (tid & 3) << 2;
    const int am   = m0 + lm;
    const int nimg = am >> (2*LOG_OW);
    const int arem = am & (OHW-1);
    const int ih0  = ((arem >> LOG_OW) << 1) - 1;
    const int iw0  = ((arem & (OW-1)) << 1) - 1;
    const float* ibase = in + (size_t)nimg*IC*IH*IW;

    const int boc = tid >> 2;
    const int bkq = (tid & 3) << 2;

    const int tm = (tid >> 4) << 2;
    const int tn = (tid & 15) << 2;

    float acc[4][4] = {};
    float pa[4]; float4 pbv;

    auto loadA = [&](int kc) {
        int k  = kc + kq;
        int ic = k >> 4;
        int ih = ih0 + ((k >> 2) & 3);
        const float* rp = ibase + ((size_t)ic*IH + ih)*IW;
        bool rowok = (unsigned)ih < (unsigned)IH;
        #pragma unroll
        for (int j = 0; j < 4; j++) {
            int iw = iw0 + j;
            pa[j] = (rowok && (unsigned)iw < (unsigned)IW) ? __ldg(rp + iw) : 0.f;
        }
    };
    auto loadB = [&](int kc) {
        pbv = *(const float4*)&w[(size_t)boc*K + kc + bkq];
    };
    auto stsA = [&](int buf) {
        #pragma unroll
        for (int j = 0; j < 4; j++) As[buf][kq+j][lm] = pa[j];
    };
    auto stsB = [&](int buf) {
        Bs[buf][bkq+0][boc] = pbv.x; Bs[buf][bkq+1][boc] = pbv.y;
        Bs[buf][bkq+2][boc] = pbv.z; Bs[buf][bkq+3][boc] = pbv.w;
    };

    loadA(0); loadB(0); stsA(0); stsB(0); __syncthreads();
    const int nch = K >> 4;
    for (int ch = 0; ch < nch; ch++) {
        int cur = ch & 1;
        if (ch + 1 < nch) { loadA((ch+1) << 4); loadB((ch+1) << 4); }
        #pragma unroll
        for (int k = 0; k < 16; k++) {
            float4 a = *(const float4*)&As[cur][k][tm];
            float4 b = *(const float4*)&Bs[cur][k][tn];
            acc[0][0] += a.x*b.x; acc[0][1] += a.x*b.y; acc[0][2] += a.x*b.z; acc[0][3] += a.x*b.w;
            acc[1][0] += a.y*b.x; acc[1][1] += a.y*b.y; acc[1][2] += a.y*b.z; acc[1][3] += a.y*b.w;
            acc[2][0] += a.z*b.x; acc[2][1] += a.z*b.y; acc[2][2] += a.z*b.z; acc[2][3] += a.z*b.w;
            acc[3][0] += a.w*b.x; acc[3][1] += a.w*b.y; acc[3][2] += a.w*b.z; acc[3][3] += a.w*b.w;
        }
        if (ch + 1 < nch) { stsA(cur ^ 1); stsB(cur ^ 1); __syncthreads(); }
    }

    const float4 bv = *(const float4*)&bias[tn];
    float b4[4] = {bv.x, bv.y, bv.z, bv.w};
    #pragma unroll
    for (int i = 0; i < 4; i++) {
        int m    = m0 + tm + i;
        int ni   = m >> (2*LOG_OW);
        int rem  = m & (OHW-1);
        __half* op = out + ((size_t)ni*64 + tn)*OHW + rem;
        #pragma unroll
        for (int j = 0; j < 4; j++) {
            float v = acc[i][j] + b4[j];
            v = v > 0.f ? v : 0.2f*v;
            op[(size_t)j*OHW] = __float2half_rn(v);
        }
    }
}

// ---------------- fp16 mma helper ----------------
__device__ __forceinline__ void mma_fp16(float* c, const unsigned* a, const unsigned* b) {
    asm volatile(
        "mma.sync.aligned.m16n8k16.row.col.f32.f16.f16.f32 "
        "{%0,%1,%2,%3}, {%4,%5,%6,%7}, {%8,%9}, {%0,%1,%2,%3};"
        : "+f"(c[0]), "+f"(c[1]), "+f"(c[2]), "+f"(c[3])
        : "r"(a[0]), "r"(a[1]), "r"(a[2]), "r"(a[3]), "r"(b[0]), "r"(b[1]));
}

// ---------------- conv2-4: fp16 single-pass MMA, BM=64 BN=128 BK=32 ------
#define MSTR 40
template<int IC, int LOG_OW>
__global__ __launch_bounds__(256) void conv_mma_kernel(
        const __half* __restrict__ Ah16, const __half* __restrict__ Wh16,
        float* __restrict__ part, int K, int Kchunk) {
    constexpr int OW = 1 << LOG_OW, OHW = OW*OW, IW = 2*OW, IH = IW;
    __shared__ __align__(16) uint16_t Ah[2][64][MSTR];
    __shared__ __align__(16) uint16_t Bh[2][128][MSTR];

    const int tid = threadIdx.x;
    const int m0  = blockIdx.x << 6;
    const int n0  = blockIdx.y << 7;
    const int NN  = gridDim.y << 7;
    const int MM  = gridDim.x << 6;
    const int k0  = blockIdx.z * Kchunk;
    float* pout = part + (size_t)blockIdx.z * MM * NN;

    // A mapping: row lm (0..63), k-range kq8..kq8+7
    const int lm  = tid >> 2;
    const int kq8 = (tid & 3) << 3;
    const int am   = m0 + lm;
    const int nimg = am >> (2*LOG_OW);
    const int arem = am & (OHW-1);
    const int ih0  = ((arem >> LOG_OW) << 1) - 1;
    const int iw0  = ((arem & (OW-1)) << 1) - 1;
    const __half* ibase = Ah16 + (size_t)nimg*IC*IH*IW;

    // B mapping: row brow (0..127), k-range bk16..bk16+15
    const int brow = tid >> 1;
    const int bk16 = (tid & 1) << 4;
    const __half* wrow = Wh16 + (size_t)(n0 + brow)*K;

    // warp layout: 2(m) x 4(n), warp tile 32x32
    const int wid  = tid >> 5, lane = tid & 31;
    const int wm   = (wid >> 2) << 5;
    const int wn   = (wid & 3) << 5;
    const int g    = lane >> 2;
    const int q    = lane & 3;

    float acc[2][4][4];
    #pragma unroll
    for (int i = 0; i < 2; i++)
        #pragma unroll
        for (int j = 0; j < 4; j++)
            #pragma unroll
            for (int e = 0; e < 4; e++) acc[i][j][e] = 0.f;

    unsigned short pa[8]; uint4 wv[2];

    auto loadA = [&](int kc) {
        int kbase = kc + kq8;
        int ic = kbase >> 4;
        #pragma unroll
        for (int grp = 0; grp < 2; grp++) {
            int k  = kbase + grp*4;
            int ih = ih0 + ((k >> 2) & 3);
            const __half* rp = ibase + ((size_t)ic*IH + ih)*IW;
            bool rowok = (unsigned)ih < (unsigned)IH;
            #pragma unroll
            for (int j = 0; j < 4; j++) {
                int iw = iw0 + j;
                __half v = __float2half_rn(0.f);
                if (rowok && (unsigned)iw < (unsigned)IW) v = __ldg(rp + iw);
                pa[grp*4 + j] = *(unsigned short*)&v;
            }
        }
    };
    auto loadB = [&](int kc) {
        wv[0] = *(const uint4*)(wrow + kc + bk16);
        wv[1] = *(const uint4*)(wrow + kc + bk16 + 8);
    };
    auto stsA = [&](int buf) {
        unsigned p0 = (unsigned)pa[0] | ((unsigned)pa[1] << 16);
        unsigned p1 = (unsigned)pa[2] | ((unsigned)pa[3] << 16);
        unsigned p2 = (unsigned)pa[4] | ((unsigned)pa[5] << 16);
        unsigned p3 = (unsigned)pa[6] | ((unsigned)pa[7] << 16);
        *(uint4*)&Ah[buf][lm][kq8] = make_uint4(p0, p1, p2, p3);
    };
    auto stsB = [&](int buf) {
        *(uint4*)&Bh[buf][brow][bk16]     = wv[0];
        *(uint4*)&Bh[buf][brow][bk16 + 8] = wv[1];
    };

    loadA(k0); loadB(k0); stsA(0); stsB(0); __syncthreads();
    const int nch = Kchunk >> 5;
    for (int ch = 0; ch < nch; ch++) {
        int cur = ch & 1;
        if (ch + 1 < nch) { loadA(k0 + ((ch+1) << 5)); loadB(k0 + ((ch+1) << 5)); }
        #pragma unroll
        for (int step = 0; step < 2; step++) {
            const int ko = step*16 + q*2;
            unsigned ah[2][4], bh[4][2];
            #pragma unroll
            for (int mf = 0; mf < 2; mf++) {
                int r = wm + mf*16 + g;
                ah[mf][0] = *(const unsigned*)&Ah[cur][r    ][ko];
                ah[mf][1] = *(const unsigned*)&Ah[cur][r + 8][ko];
                ah[mf][2] = *(const unsigned*)&Ah[cur][r    ][ko + 8];
                ah[mf][3] = *(const unsigned*)&Ah[cur][r + 8][ko + 8];
            }
            #pragma unroll
            for (int nf = 0; nf < 4; nf++) {
                int rb = wn + nf*8 + g;
                bh[nf][0] = *(const unsigned*)&Bh[cur][rb][ko];
                bh[nf][1] = *(const unsigned*)&Bh[cur][rb][ko + 8];
            }
            #pragma unroll
            for (int mf = 0; mf < 2; mf++)
                #pragma unroll
                for (int nf = 0; nf < 4; nf++)
                    mma_fp16(acc[mf][nf], ah[mf], bh[nf]);
        }
        if (ch + 1 < nch) { stsA(cur ^ 1); stsB(cur ^ 1); __syncthreads(); }
    }

    #pragma unroll
    for (int mf = 0; mf < 2; mf++) {
        #pragma unroll
        for (int nf = 0; nf < 4; nf++) {
            int r0 = m0 + wm + mf*16 + g;
            int r1 = r0 + 8;
            int c0 = n0 + wn + nf*8 + q*2;
            *(float2*)(pout + (size_t)r0*NN + c0) = make_float2(acc[mf][nf][0], acc[mf][nf][1]);
            *(float2*)(pout + (size_t)r1*NN + c0) = make_float2(acc[mf][nf][2], acc[mf][nf][3]);
        }
    }
}

// ---------------- split-K reduce + bias -> NCHW ----------------
__global__ void redk_kernel(const float* __restrict__ part, const float* __restrict__ bias,
                            float* __restrict__ out, int MN, int log_nn, int KS, int log_ohw) {
    int NNm = (1 << log_nn) - 1;
    int OHWm = (1 << log_ohw) - 1;
    for (int idx = blockIdx.x*blockDim.x + threadIdx.x; idx < MN; idx += gridDim.x*blockDim.x) {
        int m = idx >> log_nn, n = idx & NNm;
        float s = 0.f;
        for (int z = 0; z < KS; z++) s += part[(size_t)z*MN + idx];
        s += bias[n];
        int ni = m >> log_ohw, rem = m & OHWm;
        out[((((size_t)ni << log_nn) + n) << log_ohw) + rem] = s;
    }
}

// ---------------- batchnorm stats (double accum) ----------------
__global__ void bn_reduce_kernel(const float* __restrict__ x, const float* __restrict__ g,
                                 const float* __restrict__ be, int N, int C, int S) {
    int c = blockIdx.x;
    double s = 0.0, s2 = 0.0;
    int M = N*S;
    for (int j = threadIdx.x; j < M; j += blockDim.x) {
        int n = j / S, sp = j % S;
        float v = x[((size_t)n*C + c)*S + sp];
        s += (double)v; s2 += (double)v*(double)v;
    }
    __shared__ double sh[256], sh2[256];
    sh[threadIdx.x] = s; sh2[threadIdx.x] = s2; __syncthreads();
    for (int st = 128; st > 0; st >>= 1) {
        if (threadIdx.x < st) { sh[threadIdx.x] += sh[threadIdx.x+st]; sh2[threadIdx.x] += sh2[threadIdx.x+st]; }
        __syncthreads();
    }
    if (threadIdx.x == 0) {
        double mean = sh[0] / M;
        double var  = sh2[0] / M - mean*mean;
        double isd  = 1.0 / sqrt(var + 1e-5);
        float sc = (float)((double)g[c] * isd);
        g_bnscale[c] = sc;
        g_bnshift[c] = be[c] - (float)(mean * (double)sc);
    }
}

// ---------------- head: bn4+lrelu+conv5 dot+softplus+mean ----------------
__global__ void head_kernel(const float* __restrict__ a4, const float* __restrict__ w5,
                            const float* __restrict__ b5, float* __restrict__ out) {
    int tid = threadIdx.x;            // 512
    int lane = tid & 31, warp = tid >> 5;   // 16 warps
    __shared__ float slog[64];
    for (int p = warp; p < NPATCH; p += 16) {
        const float* ap = a4 + (size_t)p*8192;
        float s = 0.f;
        for (int i = lane; i < 8192; i += 32) {
            int c = i >> 4;
            float v = ap[i]*g_bnscale[c] + g_bnshift[c];
            v = v > 0.f ? v : 0.2f*v;
            s += v * w5[i];
        }
        #pragma unroll
        for (int d = 16; d > 0; d >>= 1) s += __shfl_xor_sync(0xFFFFFFFFu, s, d);
        if (lane == 0) slog[p] = s + b5[0];
    }
    __syncthreads();
    if (tid < 64) {
        float x = -slog[tid];
        slog[tid] = fmaxf(x, 0.f) + log1pf(expf(-fabsf(x)));
    }
    __syncthreads();
    if (tid < 32) {
        float v = slog[tid] + slog[tid + 32];
        #pragma unroll
        for (int d = 16; d > 0; d >>= 1) v += __shfl_xor_sync(0xFFFFFFFFu, v, d);
        if (tid == 0) out[0] = v / 64.f;
    }
}

// ---------------- launcher ----------------
extern "C" void kernel_launch(void* const* d_in, const int* in_sizes, int n_in,
                              void* d_out, int out_size) {
    const float* pred     = (const float*)d_in[0];
    const float* source   = (const float*)d_in[1];
    const int*   rand_sel = (const int*)d_in[2];
    const float* w1 = (const float*)d_in[3];  const float* b1 = (const float*)d_in[4];
    const float* w2 = (const float*)d_in[5];  const float* b2 = (const float*)d_in[6];
    const float* g2 = (const float*)d_in[7];  const float* be2= (const float*)d_in[8];
    const float* w3 = (const float*)d_in[9];  const float* b3 = (const float*)d_in[10];
    const float* g3 = (const float*)d_in[11]; const float* be3= (const float*)d_in[12];
    const float* w4 = (const float*)d_in[13]; const float* b4 = (const float*)d_in[14];
    const float* g4 = (const float*)d_in[15]; const float* be4= (const float*)d_in[16];
    const float* w5 = (const float*)d_in[17]; const float* b5 = (const float*)d_in[18];
    float* out = (float*)d_out;

    float *patches, *a2, *a3, *a4, *part;
    __half *a1h, *a2h, *a3h, *wh2, *wh3, *wh4;
    cudaGetSymbolAddress((void**)&patches, g_patches);
    cudaGetSymbolAddress((void**)&a1h, g_a1h);
    cudaGetSymbolAddress((void**)&a2h, g_a2h);
    cudaGetSymbolAddress((void**)&a3h, g_a3h);
    cudaGetSymbolAddress((void**)&a2, g_act2);
    cudaGetSymbolAddress((void**)&a3, g_act3);
    cudaGetSymbolAddress((void**)&a4, g_act4);
    cudaGetSymbolAddress((void**)&wh2, g_wh2);
    cudaGetSymbolAddress((void**)&wh3, g_wh3);
    cudaGetSymbolAddress((void**)&wh4, g_wh4);
    cudaGetSymbolAddress((void**)&part, g_part);

    // weight fp16 convert (independent of data path)
    wsplit_all_kernel<<<dim3(512, 3), 256>>>(w2, w3, w4);
    // detector + pools (hist fused into vpool)
    hpool_det_kernel<<<dim3(HH, BB), 256>>>(source);
    vpool_kernel<<<dim3(WW/32, HH/64, BB), 256>>>();
    // topk: resolve threshold, collect candidates, exact rank
    topk_resolve_kernel<<<BB, 256>>>();
    topk_collect_kernel<<<dim3(48, BB), 256>>>();
    topk_final_kernel<<<BB, 1024>>>(rand_sel);
    // patch gather
    gather_kernel<<<(NPATCH*3*PS*PS + 255)/256, 256>>>(pred);
    // conv1 (FFMA implicit GEMM, bias+lrelu fused, fp16 output)
    conv1_kernel<<<1024, 256>>>(patches, w1, b1, a1h);
    // conv2: M=16384, N=128, K=1024, split-K=2
    conv_mma_kernel<64, 4><<<dim3(256, 1, 2), 256>>>(a1h, wh2, part, 1024, 512);
    redk_kernel<<<2048, 256>>>(part, b2, a2, 16384*128, 7, 2, 8);
    bn_reduce_kernel<<<128, 256>>>(a2, g2, be2, NPATCH, 128, 16*16);
    bnsplit_kernel<<<1024, 256>>>(a2, a2h, NPATCH*128*16*16, 8, 127);
    // conv3: M=4096, N=256, K=2048, split-K=4
    conv_mma_kernel<128, 3><<<dim3(64, 2, 4), 256>>>(a2h, wh3, part, 2048, 512);
    redk_kernel<<<1024, 256>>>(part, b3, a3, 4096*256, 8, 4, 6);
    bn_reduce_kernel<<<256, 256>>>(a3, g3, be3, NPATCH, 256, 8*8);
    bnsplit_kernel<<<512, 256>>>(a3, a3h, NPATCH*256*8*8, 6, 255);
    // conv4: M=1024, N=512, K=4096, split-K=8
    conv_mma_kernel<256, 2><<<dim3(16, 4, 8), 256>>>(a3h, wh4, part, 4096, 512);
    redk_kernel<<<512, 256>>>(part, b4, a4, 1024*512, 9, 8, 4);
    bn_reduce_kernel<<<512, 256>>>(a4, g4, be4, NPATCH, 512, 4*4);
    // head: bn4+lrelu+conv5+softplus+mean
    head_kernel<<<1, 512>>>(a4, w5, b5, out);
}

// round 13
// speedup vs baseline: 1.1671x; 1.0084x over previous
#include <cuda_runtime.h>
#include <cuda_fp16.h>
#include <cstdint>
#include <math.h>

#define BB 16
#define HH 768
#define WW 768
#define NPIX (HH*WW)
#define TOPK 100
#define NP 4
#define NPATCH (BB*NP)   // 64
#define PS 64            // patch size
#define CANDCAP 16384

// ---------------- scratch (static device globals) ----------------
__device__ float g_mask[BB*NPIX];
__device__ float g_tmp[BB*NPIX];
__device__ unsigned g_hist12[BB][4096];
__device__ unsigned g_T12[BB];
__device__ int g_candn[BB];
__device__ unsigned long long g_cand[BB][CANDCAP];
__device__ int g_py[NPATCH], g_px[NPATCH];
__device__ float g_patches[NPATCH*3*PS*PS];
// +8 halfs pad; kernels use base+1 so odd half-indices are 4B-aligned
__device__ __align__(16) __half g_a1h[NPATCH*64*32*32 + 8];
__device__ __align__(16) __half g_a2h[NPATCH*128*16*16 + 8];
__device__ __align__(16) __half g_a3h[NPATCH*256*8*8 + 8];
__device__ float g_act2[NPATCH*128*16*16];
__device__ float g_act3[NPATCH*256*8*8];
__device__ float g_act4[NPATCH*512*4*4];
__device__ __half g_wh2[128*1024];
__device__ __half g_wh3[256*2048];
__device__ __half g_wh4[512*4096];
__device__ float g_part[4194304];
__device__ float g_bnscale[512], g_bnshift[512];

// ---------------- detector fused into 15-tap horizontal pool ---------------
__global__ void hpool_det_kernel(const float* __restrict__ src) {
    if (blockIdx.y == 0 && blockIdx.x < 64) {
        int base = blockIdx.x * 1024;
        for (int i = threadIdx.x; i < 1024; i += 256)
            ((unsigned*)g_hist12)[base + i] = 0u;
    }
    if (blockIdx.y == 0 && blockIdx.x == 100 && threadIdx.x < BB)
        g_candn[threadIdx.x] = 0;

    __shared__ float row[WW + 14];
    int y = blockIdx.x, b = blockIdx.y;
    const float* sb = src + ((size_t)b*3*HH + y)*WW;
    for (int i = threadIdx.x; i < WW + 14; i += blockDim.x) {
        int x = i - 7;
        float m = 0.f;
        if (x >= 0 && x < WW) {
            float r  = (sb[x]               + 1.f)*0.5f;
            float gg = (sb[(size_t)HH*WW + x]   + 1.f)*0.5f;
            float bl = (sb[(size_t)2*HH*WW + x] + 1.f)*0.5f;
            float br = 0.299f*r + 0.587f*gg + 0.114f*bl;
            float bm = 1.f/(1.f + expf(-20.f*(br - 0.65f)));
            float mx = fmaxf(r, fmaxf(gg, bl));
            float mn = fminf(r, fminf(gg, bl));
            float ls = 1.f/(1.f + expf(-20.f*(0.15f - (mx - mn))));
            m = bm*ls;
        }
        row[i] = m;
    }
    __syncthreads();
    float* op = g_tmp + ((size_t)b*HH + y)*WW;
    for (int x = threadIdx.x; x < WW; x += blockDim.x) {
        float s = 0.f;
        #pragma unroll
        for (int d = 0; d < 15; d++) s += row[x + d];
        op[x] = s;
    }
}

// ---------------- 15-tap vertical sum + /225 -> g_mask, + 12-bit hist -----
__global__ void vpool_kernel() {
    __shared__ float tile[78][32];
    __shared__ unsigned shist[4096];
    int c0 = blockIdx.x*32, r0 = blockIdx.y*64, b = blockIdx.z;
    for (int i = threadIdx.x; i < 4096; i += blockDim.x) shist[i] = 0u;
    const float* ip = g_tmp + (size_t)b*NPIX;
    for (int i = threadIdx.x; i < 78*32; i += blockDim.x) {
        int r = i >> 5, c = i & 31;
        int y = r0 + r - 7;
        tile[r][c] = (y >= 0 && y < HH) ? ip[(size_t)y*WW + c0 + c] : 0.f;
    }
    __syncthreads();
    float* op = g_mask + (size_t)b*NPIX;
    int c = threadIdx.x & 31;
    for (int rr = threadIdx.x >> 5; rr < 64; rr += blockDim.x >> 5) {
        float s = 0.f;
        #pragma unroll
        for (int d = 0; d < 15; d++) s += tile[rr + d][c];
        float v = s / 225.0f;
        op[(size_t)(r0 + rr)*WW + c0 + c] = v;
        atomicAdd(&shist[__float_as_uint(v) >> 20], 1u);
    }
    __syncthreads();
    for (int i = threadIdx.x; i < 4096; i += blockDim.x) {
        unsigned cc = shist[i];
        if (cc) atomicAdd(&g_hist12[b][i], cc);
    }
}

// ---------------- resolve 12-bit threshold ----------------
__global__ void topk_resolve_kernel() {
    int b = blockIdx.x, t = threadIdx.x;   // 256 threads
    __shared__ unsigned csum[257];
    __shared__ int s_c;
    unsigned s = 0;
    #pragma unroll
    for (int j = 0; j < 16; j++) s += g_hist12[b][t*16 + j];
    csum[t] = s;
    if (t == 0) csum[256] = 0;
    __syncthreads();
    for (int off = 1; off < 256; off <<= 1) {
        unsigned v = csum[t] + ((t + off < 256) ? csum[t + off] : 0u);
        __syncthreads();
        csum[t] = v;
        __syncthreads();
    }
    if (csum[t] >= TOPK && (t == 255 || csum[t + 1] < TOPK)) s_c = t;
    __syncthreads();
    if (t == 0) {
        int cch = s_c;
        unsigned running = (cch == 255) ? 0u : csum[cch + 1];
        unsigned T = (unsigned)(cch*16);
        for (int bin = cch*16 + 15; bin >= cch*16; bin--) {
            running += g_hist12[b][bin];
            if (running >= TOPK) { T = (unsigned)bin; break; }
        }
        g_T12[b] = T;
    }
}

// ---------------- collect candidates (one full scan, grid-wide) ----------
__global__ void topk_collect_kernel() {
    int b = blockIdx.y;
    unsigned T = g_T12[b];
    const float4* wp4 = (const float4*)(g_mask + (size_t)b*NPIX);
    for (int i = blockIdx.x*blockDim.x + threadIdx.x; i < NPIX/4; i += gridDim.x*blockDim.x) {
        float4 v = wp4[i];
        unsigned kk[4] = {__float_as_uint(v.x), __float_as_uint(v.y),
                          __float_as_uint(v.z), __float_as_uint(v.w)};
        #pragma unroll
        for (int j = 0; j < 4; j++) {
            if ((kk[j] >> 20) >= T) {
                int p = atomicAdd(&g_candn[b], 1);
                if (p < CANDCAP)
                    g_cand[b][p] = ((unsigned long long)kk[j] << 32)
                                 | (unsigned)(0xFFFFFFFFu - (unsigned)(4*i + j));
            }
        }
    }
}

// ---------------- exact top-100 by rank + coords ----------------
__global__ __launch_bounds__(1024) void topk_final_kernel(const int* __restrict__ rand_sel) {
    int b = blockIdx.x, tid = threadIdx.x;
    __shared__ unsigned long long ch[2048];
    __shared__ int stop[TOPK];
    int n = min(g_candn[b], CANDCAP);
    unsigned long long vi[16]; int ri[16]; int nc = 0;
    for (int i = tid; i < n; i += 1024) {
        if (nc < 16) { vi[nc] = g_cand[b][i]; ri[nc] = 0; nc++; }
    }
    for (int base = 0; base < n; base += 2048) {
        int len = min(2048, n - base);
        for (int j = tid; j < len; j += 1024) ch[j] = g_cand[b][base + j];
        __syncthreads();
        for (int cnd = 0; cnd < nc; cnd++) {
            unsigned long long v = vi[cnd]; int r = 0;
            for (int j = 0; j < len; j++) r += (ch[j] > v) ? 1 : 0;
            ri[cnd] += r;
        }
        __syncthreads();
    }
    for (int cnd = 0; cnd < nc; cnd++)
        if (ri[cnd] < TOPK)
            stop[ri[cnd]] = (int)(0xFFFFFFFFu - (unsigned)(vi[cnd] & 0xFFFFFFFFu));
    __syncthreads();
    if (tid < NP) {
        int r = rand_sel[b*NP + tid];
        int sel = stop[r];
        int y = sel / WW - PS/2; y = max(0, min(y, HH - PS));
        int x = sel % WW - PS/2; x = max(0, min(x, WW - PS));
        g_py[b*NP + tid] = y; g_px[b*NP + tid] = x;
    }
}

// ---------------- patch gather ----------------
__global__ void gather_kernel(const float* __restrict__ pred) {
    int idx = blockIdx.x*blockDim.x + threadIdx.x;
    const int total = NPATCH*3*PS*PS;
    if (idx >= total) return;
    int j = idx & 63; int t = idx >> 6;
    int i = t & 63;   t >>= 6;
    int c = t % 3;    int p = t / 3;
    int b = p >> 2;
    g_patches[idx] = pred[(((size_t)b*3 + c)*HH + g_py[p] + i)*WW + g_px[p] + j];
}

// ---------------- weight convert: fp32 -> fp16 ----------------
__global__ void wsplit_all_kernel(const float* __restrict__ w2,
                                  const float* __restrict__ w3,
                                  const float* __restrict__ w4) {
    int which = blockIdx.y;
    const float* w = (which == 0) ? w2 : (which == 1) ? w3 : w4;
    __half* o = (which == 0) ? g_wh2 : (which == 1) ? g_wh3 : g_wh4;
    int n = (which == 0) ? 131072 : (which == 1) ? 524288 : 2097152;
    for (int i = blockIdx.x*blockDim.x + threadIdx.x; i < n; i += gridDim.x*blockDim.x)
        o[i] = __float2half_rn(w[i]);
}

// ---------------- bn apply + lrelu + fp16 convert ----------------
__global__ void bnsplit_kernel(const float* __restrict__ x, __half* __restrict__ o,
                               int total, int log_s, int cmask) {
    for (int idx = blockIdx.x*blockDim.x + threadIdx.x; idx < total; idx += gridDim.x*blockDim.x) {
        int c = (idx >> log_s) & cmask;
        float v = x[idx]*g_bnscale[c] + g_bnshift[c];
        v = v > 0.f ? v : 0.2f*v;
        o[idx] = __float2half_rn(v);
    }
}

// ---------------- conv1: implicit GEMM 64x64 FFMA, K=48, fp16 output ----
__global__ __launch_bounds__(256) void conv1_kernel(
        const float* __restrict__ in, const float* __restrict__ w,
        const float* __restrict__ bias, __half* __restrict__ out) {
    constexpr int IC = 3, LOG_OW = 5, OW = 32, OHW = OW*OW, IW = 64, IH = 64, K = 48;
    __shared__ __align__(16) float As[2][16][68];
    __shared__ __align__(16) float Bs[2][16][68];
    const int tid = threadIdx.x;
    const int m0  = blockIdx.x << 6;

    const int lm = tid >> 2;
    const int kq = (tid & 3) << 2;
    const int am   = m0 + lm;
    const int nimg = am >> (2*LOG_OW);
    const int arem = am & (OHW-1);
    const int ih0  = ((arem >> LOG_OW) << 1) - 1;
    const int iw0  = ((arem & (OW-1)) << 1) - 1;
    const float* ibase = in + (size_t)nimg*IC*IH*IW;

    const int boc = tid >> 2;
    const int bkq = (tid & 3) << 2;

    const int tm = (tid >> 4) << 2;
    const int tn = (tid & 15) << 2;

    float acc[4][4] = {};
    float pa[4]; float4 pbv;

    auto loadA = [&](int kc) {
        int k  = kc + kq;
        int ic = k >> 4;
        int ih = ih0 + ((k >> 2) & 3);
        const float* rp = ibase + ((size_t)ic*IH + ih)*IW;
        bool rowok = (unsigned)ih < (unsigned)IH;
        #pragma unroll
        for (int j = 0; j < 4; j++) {
            int iw = iw0 + j;
            pa[j] = (rowok && (unsigned)iw < (unsigned)IW) ? __ldg(rp + iw) : 0.f;
        }
    };
    auto loadB = [&](int kc) {
        pbv = *(const float4*)&w[(size_t)boc*K + kc + bkq];
    };
    auto stsA = [&](int buf) {
        #pragma unroll
        for (int j = 0; j < 4; j++) As[buf][kq+j][lm] = pa[j];
    };
    auto stsB = [&](int buf) {
        Bs[buf][bkq+0][boc] = pbv.x; Bs[buf][bkq+1][boc] = pbv.y;
        Bs[buf][bkq+2][boc] = pbv.z; Bs[buf][bkq+3][boc] = pbv.w;
    };

    loadA(0); loadB(0); stsA(0); stsB(0); __syncthreads();
    const int nch = K >> 4;
    for (int ch = 0; ch < nch; ch++) {
        int cur = ch & 1;
        if (ch + 1 < nch) { loadA((ch+1) << 4); loadB((ch+1) << 4); }
        #pragma unroll
        for (int k = 0; k < 16; k++) {
            float4 a = *(const float4*)&As[cur][k][tm];
            float4 b = *(const float4*)&Bs[cur][k][tn];
            acc[0][0] += a.x*b.x; acc[0][1] += a.x*b.y; acc[0][2] += a.x*b.z; acc[0][3] += a.x*b.w;
            acc[1][0] += a.y*b.x; acc[1][1] += a.y*b.y; acc[1][2] += a.y*b.z; acc[1][3] += a.y*b.w;
            acc[2][0] += a.z*b.x; acc[2][1] += a.z*b.y; acc[2][2] += a.z*b.z; acc[2][3] += a.z*b.w;
            acc[3][0] += a.w*b.x; acc[3][1] += a.w*b.y; acc[3][2] += a.w*b.z; acc[3][3] += a.w*b.w;
        }
        if (ch + 1 < nch) { stsA(cur ^ 1); stsB(cur ^ 1); __syncthreads(); }
    }

    const float4 bv = *(const float4*)&bias[tn];
    float b4[4] = {bv.x, bv.y, bv.z, bv.w};
    #pragma unroll
    for (int i = 0; i < 4; i++) {
        int m    = m0 + tm + i;
        int ni   = m >> (2*LOG_OW);
        int rem  = m & (OHW-1);
        __half* op = out + ((size_t)ni*64 + tn)*OHW + rem;
        #pragma unroll
        for (int j = 0; j < 4; j++) {
            float v = acc[i][j] + b4[j];
            v = v > 0.f ? v : 0.2f*v;
            op[(size_t)j*OHW] = __float2half_rn(v);
        }
    }
}

// ---------------- fp16 mma helper ----------------
__device__ __forceinline__ void mma_fp16(float* c, const unsigned* a, const unsigned* b) {
    asm volatile(
        "mma.sync.aligned.m16n8k16.row.col.f32.f16.f16.f32 "
        "{%0,%1,%2,%3}, {%4,%5,%6,%7}, {%8,%9}, {%0,%1,%2,%3};"
        : "+f"(c[0]), "+f"(c[1]), "+f"(c[2]), "+f"(c[3])
        : "r"(a[0]), "r"(a[1]), "r"(a[2]), "r"(a[3]), "r"(b[0]), "r"(b[1]));
}

// ---------------- conv2-4: fp16 single-pass MMA, BM=64 BN=128 BK=32 ------
// A loads vectorized: activations stored at +1-half offset so all odd iw
// indices (iw0 = 2*ow-1) are 4B-aligned -> 2x LDG.32 per 4-half window.
#define MSTR 40
template<int IC, int LOG_OW, bool DIRECT>
__global__ __launch_bounds__(256) void conv_mma_kernel(
        const __half* __restrict__ Ah16, const __half* __restrict__ Wh16,
        const float* __restrict__ bias, float* __restrict__ outd,
        float* __restrict__ part, int K, int Kchunk) {
    constexpr int OW = 1 << LOG_OW, OHW = OW*OW, IW = 2*OW, IH = IW;
    __shared__ __align__(16) uint16_t Ah[2][64][MSTR];
    __shared__ __align__(16) uint16_t Bh[2][128][MSTR];

    const int tid = threadIdx.x;
    const int m0  = blockIdx.x << 6;
    const int n0  = blockIdx.y << 7;
    const int NN  = gridDim.y << 7;
    const int MM  = gridDim.x << 6;
    const int k0  = blockIdx.z * Kchunk;
    float* pout = part + (size_t)blockIdx.z * MM * NN;

    // A mapping: row lm (0..63), k-range kq8..kq8+7
    const int lm  = tid >> 2;
    const int kq8 = (tid & 3) << 3;
    const int am   = m0 + lm;
    const int nimg = am >> (2*LOG_OW);
    const int arem = am & (OHW-1);
    const int owx  = arem & (OW-1);
    const int ih0  = ((arem >> LOG_OW) << 1) - 1;
    const int iw0  = (owx << 1) - 1;
    const bool interior = (owx >= 1) && (owx <= OW-2);
    const __half* ibase = Ah16 + (size_t)nimg*IC*IH*IW;

    // B mapping: row brow (0..127), k-range bk16..bk16+15
    const int brow = tid >> 1;
    const int bk16 = (tid & 1) << 4;
    const __half* wrow = Wh16 + (size_t)(n0 + brow)*K;

    // warp layout: 2(m) x 4(n), warp tile 32x32
    const int wid  = tid >> 5, lane = tid & 31;
    const int wm   = (wid >> 2) << 5;
    const int wn   = (wid & 3) << 5;
    const int g    = lane >> 2;
    const int q    = lane & 3;

    float acc[2][4][4];
    #pragma unroll
    for (int i = 0; i < 2; i++)
        #pragma unroll
        for (int j = 0; j < 4; j++)
            #pragma unroll
            for (int e = 0; e < 4; e++) acc[i][j][e] = 0.f;

    unsigned paw[4]; uint4 wv[2];

    auto loadA = [&](int kc) {
        int kbase = kc + kq8;
        int ic = kbase >> 4;
        #pragma unroll
        for (int grp = 0; grp < 2; grp++) {
            int k  = kbase + grp*4;
            int ih = ih0 + ((k >> 2) & 3);
            const __half* rp = ibase + ((size_t)ic*IH + ih)*IW;
            bool rowok = (unsigned)ih < (unsigned)IH;
            unsigned u0 = 0u, u1 = 0u;
            if (rowok) {
                if (interior) {
                    u0 = __ldg((const unsigned*)(rp + iw0));
                    u1 = __ldg((const unsigned*)(rp + iw0 + 2));
                } else {
                    unsigned short h[4];
                    #pragma unroll
                    for (int j = 0; j < 4; j++) {
                        int iw = iw0 + j;
                        __half v = __ushort_as_half((unsigned short)0);
                        if ((unsigned)iw < (unsigned)IW) v = __ldg(rp + iw);
                        h[j] = __half_as_ushort(v);
                    }
                    u0 = (unsigned)h[0] | ((unsigned)h[1] << 16);
                    u1 = (unsigned)h[2] | ((unsigned)h[3] << 16);
                }
            }
            paw[grp*2]     = u0;
            paw[grp*2 + 1] = u1;
        }
    };
    auto loadB = [&](int kc) {
        wv[0] = *(const uint4*)(wrow + kc + bk16);
        wv[1] = *(const uint4*)(wrow + kc + bk16 + 8);
    };
    auto stsA = [&](int buf) {
        *(uint4*)&Ah[buf][lm][kq8] = make_uint4(paw[0], paw[1], paw[2], paw[3]);
    };
    auto stsB = [&](int buf) {
        *(uint4*)&Bh[buf][brow][bk16]     = wv[0];
        *(uint4*)&Bh[buf][brow][bk16 + 8] = wv[1];
    };

    loadA(k0); loadB(k0); stsA(0); stsB(0); __syncthreads();
    const int nch = Kchunk >> 5;
    for (int ch = 0; ch < nch; ch++) {
        int cur = ch & 1;
        if (ch + 1 < nch) { loadA(k0 + ((ch+1) << 5)); loadB(k0 + ((ch+1) << 5)); }
        #pragma unroll
        for (int step = 0; step < 2; step++) {
            const int ko = step*16 + q*2;
            unsigned ah[2][4], bh[4][2];
            #pragma unroll
            for (int mf = 0; mf < 2; mf++) {
                int r = wm + mf*16 + g;
                ah[mf][0] = *(const unsigned*)&Ah[cur][r    ][ko];
                ah[mf][1] = *(const unsigned*)&Ah[cur][r + 8][ko];
                ah[mf][2] = *(const unsigned*)&Ah[cur][r    ][ko + 8];
                ah[mf][3] = *(const unsigned*)&Ah[cur][r + 8][ko + 8];
            }
            #pragma unroll
            for (int nf = 0; nf < 4; nf++) {
                int rb = wn + nf*8 + g;
                bh[nf][0] = *(const unsigned*)&Bh[cur][rb][ko];
                bh[nf][1] = *(const unsigned*)&Bh[cur][rb][ko + 8];
            }
            #pragma unroll
            for (int mf = 0; mf < 2; mf++)
                #pragma unroll
                for (int nf = 0; nf < 4; nf++)
                    mma_fp16(acc[mf][nf], ah[mf], bh[nf]);
        }
        if (ch + 1 < nch) { stsA(cur ^ 1); stsB(cur ^ 1); __syncthreads(); }
    }

    #pragma unroll
    for (int mf = 0; mf < 2; mf++) {
        #pragma unroll
        for (int nf = 0; nf < 4; nf++) {
            int r0 = m0 + wm + mf*16 + g;
            int r1 = r0 + 8;
            int c0 = n0 + wn + nf*8 + q*2;
            if (DIRECT) {
                float bv0 = __ldg(bias + c0), bv1 = __ldg(bias + c0 + 1);
                int i0 = r0 >> (2*LOG_OW), e0 = r0 & (OHW-1);
                int i1 = r1 >> (2*LOG_OW), e1 = r1 & (OHW-1);
                float* o0 = outd + ((size_t)i0*NN + c0)*OHW + e0;
                float* o1 = outd + ((size_t)i1*NN + c0)*OHW + e1;
                o0[0]   = acc[mf][nf][0] + bv0;
                o0[OHW] = acc[mf][nf][1] + bv1;
                o1[0]   = acc[mf][nf][2] + bv0;
                o1[OHW] = acc[mf][nf][3] + bv1;
            } else {
                *(float2*)(pout + (size_t)r0*NN + c0) = make_float2(acc[mf][nf][0], acc[mf][nf][1]);
                *(float2*)(pout + (size_t)r1*NN + c0) = make_float2(acc[mf][nf][2], acc[mf][nf][3]);
            }
        }
    }
}

// ---------------- split-K reduce + bias -> NCHW ----------------
__global__ void redk_kernel(const float* __restrict__ part, const float* __restrict__ bias,
                            float* __restrict__ out, int MN, int log_nn, int KS, int log_ohw) {
    int NNm = (1 << log_nn) - 1;
    int OHWm = (1 << log_ohw) - 1;
    for (int idx = blockIdx.x*blockDim.x + threadIdx.x; idx < MN; idx += gridDim.x*blockDim.x) {
        int m = idx >> log_nn, n = idx & NNm;
        float s = 0.f;
        for (int z = 0; z < KS; z++) s += part[(size_t)z*MN + idx];
        s += bias[n];
        int ni = m >> log_ohw, rem = m & OHWm;
        out[((((size_t)ni << log_nn) + n) << log_ohw) + rem] = s;
    }
}

// ---------------- batchnorm stats (double accum) ----------------
__global__ void bn_reduce_kernel(const float* __restrict__ x, const float* __restrict__ g,
                                 const float* __restrict__ be, int N, int C, int S) {
    int c = blockIdx.x;
    double s = 0.0, s2 = 0.0;
    int M = N*S;
    for (int j = threadIdx.x; j < M; j += blockDim.x) {
        int n = j / S, sp = j % S;
        float v = x[((size_t)n*C + c)*S + sp];
        s += (double)v; s2 += (double)v*(double)v;
    }
    __shared__ double sh[256], sh2[256];
    sh[threadIdx.x] = s; sh2[threadIdx.x] = s2; __syncthreads();
    for (int st = 128; st > 0; st >>= 1) {
        if (threadIdx.x < st) { sh[threadIdx.x] += sh[threadIdx.x+st]; sh2[threadIdx.x] += sh2[threadIdx.x+st]; }
        __syncthreads();
    }
    if (threadIdx.x == 0) {
        double mean = sh[0] / M;
        double var  = sh2[0] / M - mean*mean;
        double isd  = 1.0 / sqrt(var + 1e-5);
        float sc = (float)((double)g[c] * isd);
        g_bnscale[c] = sc;
        g_bnshift[c] = be[c] - (float)(mean * (double)sc);
    }
}

// ---------------- head: bn4+lrelu+conv5 dot+softplus+mean ----------------
__global__ void head_kernel(const float* __restrict__ a4, const float* __restrict__ w5,
                            const float* __restrict__ b5, float* __restrict__ out) {
    int tid = threadIdx.x;            // 512
    int lane = tid & 31, warp = tid >> 5;   // 16 warps
    __shared__ float slog[64];
    for (int p = warp; p < NPATCH; p += 16) {
        const float* ap = a4 + (size_t)p*8192;
        float s = 0.f;
        for (int i = lane; i < 8192; i += 32) {
            int c = i >> 4;
            float v = ap[i]*g_bnscale[c] + g_bnshift[c];
            v = v > 0.f ? v : 0.2f*v;
            s += v * w5[i];
        }
        #pragma unroll
        for (int d = 16; d > 0; d >>= 1) s += __shfl_xor_sync(0xFFFFFFFFu, s, d);
        if (lane == 0) slog[p] = s + b5[0];
    }
    __syncthreads();
    if (tid < 64) {
        float x = -slog[tid];
        slog[tid] = fmaxf(x, 0.f) + log1pf(expf(-fabsf(x)));
    }
    __syncthreads();
    if (tid < 32) {
        float v = slog[tid] + slog[tid + 32];
        #pragma unroll
        for (int d = 16; d > 0; d >>= 1) v += __shfl_xor_sync(0xFFFFFFFFu, v, d);
        if (tid == 0) out[0] = v / 64.f;
    }
}

// ---------------- launcher ----------------
extern "C" void kernel_launch(void* const* d_in, const int* in_sizes, int n_in,
                              void* d_out, int out_size) {
    const float* pred     = (const float*)d_in[0];
    const float* source   = (const float*)d_in[1];
    const int*   rand_sel = (const int*)d_in[2];
    const float* w1 = (const float*)d_in[3];  const float* b1 = (const float*)d_in[4];
    const float* w2 = (const float*)d_in[5];  const float* b2 = (const float*)d_in[6];
    const float* g2 = (const float*)d_in[7];  const float* be2= (const float*)d_in[8];
    const float* w3 = (const float*)d_in[9];  const float* b3 = (const float*)d_in[10];
    const float* g3 = (const float*)d_in[11]; const float* be3= (const float*)d_in[12];
    const float* w4 = (const float*)d_in[13]; const float* b4 = (const float*)d_in[14];
    const float* g4 = (const float*)d_in[15]; const float* be4= (const float*)d_in[16];
    const float* w5 = (const float*)d_in[17]; const float* b5 = (const float*)d_in[18];
    float* out = (float*)d_out;

    float *patches, *a2, *a3, *a4, *part;
    __half *a1h, *a2h, *a3h, *wh2, *wh3, *wh4;
    cudaGetSymbolAddress((void**)&patches, g_patches);
    cudaGetSymbolAddress((void**)&a1h, g_a1h);
    cudaGetSymbolAddress((void**)&a2h, g_a2h);
    cudaGetSymbolAddress((void**)&a3h, g_a3h);
    cudaGetSymbolAddress((void**)&a2, g_act2);
    cudaGetSymbolAddress((void**)&a3, g_act3);
    cudaGetSymbolAddress((void**)&a4, g_act4);
    cudaGetSymbolAddress((void**)&wh2, g_wh2);
    cudaGetSymbolAddress((void**)&wh3, g_wh3);
    cudaGetSymbolAddress((void**)&wh4, g_wh4);
    cudaGetSymbolAddress((void**)&part, g_part);
    // +1-half shift: makes all odd half-indices 4-byte aligned
    a1h += 1; a2h += 1; a3h += 1;

    // weight fp16 convert (independent of data path)
    wsplit_all_kernel<<<dim3(512, 3), 256>>>(w2, w3, w4);
    // detector + pools (hist fused into vpool)
    hpool_det_kernel<<<dim3(HH, BB), 256>>>(source);
    vpool_kernel<<<dim3(WW/32, HH/64, BB), 256>>>();
    // topk: resolve threshold, collect candidates, exact rank
    topk_resolve_kernel<<<BB, 256>>>();
    topk_collect_kernel<<<dim3(48, BB), 256>>>();
    topk_final_kernel<<<BB, 1024>>>(rand_sel);
    // patch gather
    gather_kernel<<<(NPATCH*3*PS*PS + 255)/256, 256>>>(pred);
    // conv1 (FFMA implicit GEMM, bias+lrelu fused, fp16 output)
    conv1_kernel<<<1024, 256>>>(patches, w1, b1, a1h);
    // conv2: M=16384, N=128, K=1024 — no split-K, direct NCHW+bias
    conv_mma_kernel<64, 4, true><<<dim3(256, 1, 1), 256>>>(a1h, wh2, b2, a2, nullptr, 1024, 1024);
    bn_reduce_kernel<<<128, 256>>>(a2, g2, be2, NPATCH, 128, 16*16);
    bnsplit_kernel<<<1024, 256>>>(a2, a2h, NPATCH*128*16*16, 8, 127);
    // conv3: M=4096, N=256, K=2048, split-K=4
    conv_mma_kernel<128, 3, false><<<dim3(64, 2, 4), 256>>>(a2h, wh3, nullptr, nullptr, part, 2048, 512);
    redk_kernel<<<1024, 256>>>(part, b3, a3, 4096*256, 8, 4, 6);
    bn_reduce_kernel<<<256, 256>>>(a3, g3, be3, NPATCH, 256, 8*8);
    bnsplit_kernel<<<512, 256>>>(a3, a3h, NPATCH*256*8*8, 6, 255);
    // conv4: M=1024, N=512, K=4096, split-K=8
    conv_mma_kernel<256, 2, false><<<dim3(16, 4, 8), 256>>>(a3h, wh4, nullptr, nullptr, part, 4096, 512);
    redk_kernel<<<512, 256>>>(part, b4, a4, 1024*512, 9, 8, 4);
    bn_reduce_kernel<<<512, 256>>>(a4, g4, be4, NPATCH, 512, 4*4);
    // head: bn4+lrelu+conv5+softplus+mean
    head_kernel<<<1, 512>>>(a4, w5, b5, out);
}

// round 16
// speedup vs baseline: 1.5422x; 1.3214x over previous
#include <cuda_runtime.h>
#include <cuda_fp16.h>
#include <cstdint>
#include <math.h>

#define BB 16
#define HH 768
#define WW 768
#define NPIX (HH*WW)
#define TOPK 100
#define NP 4
#define NPATCH (BB*NP)   // 64
#define PS 64            // patch size
#define CANDCAP 16384

// ---------------- scratch (static device globals) ----------------
__device__ float g_mask[BB*NPIX];
__device__ float g_tmp[BB*NPIX];
__device__ unsigned g_hist12[BB][4096];
__device__ unsigned g_T12[BB];
__device__ int g_candn[BB];
__device__ unsigned long long g_cand[BB][CANDCAP];
__device__ int g_py[NPATCH], g_px[NPATCH];
// +8 halfs pad; kernels use base+1 so odd half-indices are 4B-aligned
__device__ __align__(16) __half g_a1h[NPATCH*64*32*32 + 8];
__device__ float g_act2[NPATCH*128*16*16];
__device__ float g_act3[NPATCH*256*8*8];
__device__ float g_act4[NPATCH*512*4*4];
__device__ __half g_wh2[128*1024];
__device__ __half g_wh3[256*2048];
__device__ __half g_wh4[512*4096];
__device__ float g_part[4194304];
__device__ float g_bnscale[512], g_bnshift[512];
__device__ float g_logits[NPATCH];

// ---------------- weight convert: fp32 -> fp16 (3 small launches) --------
__global__ void wsplit_kernel(const float* __restrict__ w, __half* __restrict__ o, int n) {
    for (int i = blockIdx.x*blockDim.x + threadIdx.x; i < n; i += gridDim.x*blockDim.x)
        o[i] = __float2half_rn(w[i]);
}

// ---------------- detector fused into 15-tap horizontal pool ---------------
__global__ void hpool_det_kernel(const float* __restrict__ src) {
    if (blockIdx.y == 0 && blockIdx.x < 64) {
        int base = blockIdx.x * 1024;
        for (int i = threadIdx.x; i < 1024; i += 256)
            ((unsigned*)g_hist12)[base + i] = 0u;
    }
    if (blockIdx.y == 0 && blockIdx.x == 100 && threadIdx.x < BB)
        g_candn[threadIdx.x] = 0;

    __shared__ float row[WW + 14];
    int y = blockIdx.x, b = blockIdx.y;
    const float* sb = src + ((size_t)b*3*HH + y)*WW;
    for (int i = threadIdx.x; i < WW + 14; i += blockDim.x) {
        int x = i - 7;
        float m = 0.f;
        if (x >= 0 && x < WW) {
            float r  = (sb[x]               + 1.f)*0.5f;
            float gg = (sb[(size_t)HH*WW + x]   + 1.f)*0.5f;
            float bl = (sb[(size_t)2*HH*WW + x] + 1.f)*0.5f;
            float br = 0.299f*r + 0.587f*gg + 0.114f*bl;
            float bm = 1.f/(1.f + expf(-20.f*(br - 0.65f)));
            float mx = fmaxf(r, fmaxf(gg, bl));
            float mn = fminf(r, fminf(gg, bl));
            float ls = 1.f/(1.f + expf(-20.f*(0.15f - (mx - mn))));
            m = bm*ls;
        }
        row[i] = m;
    }
    __syncthreads();
    float* op = g_tmp + ((size_t)b*HH + y)*WW;
    for (int x = threadIdx.x; x < WW; x += blockDim.x) {
        float s = 0.f;
        #pragma unroll
        for (int d = 0; d < 15; d++) s += row[x + d];
        op[x] = s;
    }
}

// ---------------- 15-tap vertical sum + /225 -> g_mask, + 12-bit hist -----
__global__ void vpool_kernel() {
    __shared__ float tile[78][32];
    __shared__ unsigned shist[4096];
    int c0 = blockIdx.x*32, r0 = blockIdx.y*64, b = blockIdx.z;
    for (int i = threadIdx.x; i < 4096; i += blockDim.x) shist[i] = 0u;
    const float* ip = g_tmp + (size_t)b*NPIX;
    for (int i = threadIdx.x; i < 78*32; i += blockDim.x) {
        int r = i >> 5, c = i & 31;
        int y = r0 + r - 7;
        tile[r][c] = (y >= 0 && y < HH) ? ip[(size_t)y*WW + c0 + c] : 0.f;
    }
    __syncthreads();
    float* op = g_mask + (size_t)b*NPIX;
    int c = threadIdx.x & 31;
    for (int rr = threadIdx.x >> 5; rr < 64; rr += blockDim.x >> 5) {
        float s = 0.f;
        #pragma unroll
        for (int d = 0; d < 15; d++) s += tile[rr + d][c];
        float v = s / 225.0f;
        op[(size_t)(r0 + rr)*WW + c0 + c] = v;
        atomicAdd(&shist[__float_as_uint(v) >> 20], 1u);
    }
    __syncthreads();
    for (int i = threadIdx.x; i < 4096; i += blockDim.x) {
        unsigned cc = shist[i];
        if (cc) atomicAdd(&g_hist12[b][i], cc);
    }
}

// ---------------- resolve 12-bit threshold ----------------
__global__ void topk_resolve_kernel() {
    int b = blockIdx.x, t = threadIdx.x;   // 256 threads
    __shared__ unsigned csum[257];
    __shared__ int s_c;
    unsigned s = 0;
    #pragma unroll
    for (int j = 0; j < 16; j++) s += g_hist12[b][t*16 + j];
    csum[t] = s;
    if (t == 0) csum[256] = 0;
    __syncthreads();
    for (int off = 1; off < 256; off <<= 1) {
        unsigned v = csum[t] + ((t + off < 256) ? csum[t + off] : 0u);
        __syncthreads();
        csum[t] = v;
        __syncthreads();
    }
    if (csum[t] >= TOPK && (t == 255 || csum[t + 1] < TOPK)) s_c = t;
    __syncthreads();
    if (t == 0) {
        int cch = s_c;
        unsigned running = (cch == 255) ? 0u : csum[cch + 1];
        unsigned T = (unsigned)(cch*16);
        for (int bin = cch*16 + 15; bin >= cch*16; bin--) {
            running += g_hist12[b][bin];
            if (running >= TOPK) { T = (unsigned)bin; break; }
        }
        g_T12[b] = T;
    }
}

// ---------------- collect candidates (one full scan, grid-wide) ----------
__global__ void topk_collect_kernel() {
    int b = blockIdx.y;
    unsigned T = g_T12[b];
    const float4* wp4 = (const float4*)(g_mask + (size_t)b*NPIX);
    for (int i = blockIdx.x*blockDim.x + threadIdx.x; i < NPIX/4; i += gridDim.x*blockDim.x) {
        float4 v = wp4[i];
        unsigned kk[4] = {__float_as_uint(v.x), __float_as_uint(v.y),
                          __float_as_uint(v.z), __float_as_uint(v.w)};
        #pragma unroll
        for (int j = 0; j < 4; j++) {
            if ((kk[j] >> 20) >= T) {
                int p = atomicAdd(&g_candn[b], 1);
                if (p < CANDCAP)
                    g_cand[b][p] = ((unsigned long long)kk[j] << 32)
                                 | (unsigned)(0xFFFFFFFFu - (unsigned)(4*i + j));
            }
        }
    }
}

// ---------------- exact top-100 by rank + coords ----------------
__global__ __launch_bounds__(1024) void topk_final_kernel(const int* __restrict__ rand_sel) {
    int b = blockIdx.x, tid = threadIdx.x;
    __shared__ unsigned long long ch[2048];
    __shared__ int stop[TOPK];
    int n = min(g_candn[b], CANDCAP);
    unsigned long long vi[16]; int ri[16]; int nc = 0;
    for (int i = tid; i < n; i += 1024) {
        if (nc < 16) { vi[nc] = g_cand[b][i]; ri[nc] = 0; nc++; }
    }
    for (int base = 0; base < n; base += 2048) {
        int len = min(2048, n - base);
        for (int j = tid; j < len; j += 1024) ch[j] = g_cand[b][base + j];
        __syncthreads();
        for (int cnd = 0; cnd < nc; cnd++) {
            unsigned long long v = vi[cnd]; int r = 0;
            for (int j = 0; j < len; j++) r += (ch[j] > v) ? 1 : 0;
            ri[cnd] += r;
        }
        __syncthreads();
    }
    for (int cnd = 0; cnd < nc; cnd++)
        if (ri[cnd] < TOPK)
            stop[ri[cnd]] = (int)(0xFFFFFFFFu - (unsigned)(vi[cnd] & 0xFFFFFFFFu));
    __syncthreads();
    if (tid < NP) {
        int r = rand_sel[b*NP + tid];
        int sel = stop[r];
        int y = sel / WW - PS/2; y = max(0, min(y, HH - PS));
        int x = sel % WW - PS/2; x = max(0, min(x, WW - PS));
        g_py[b*NP + tid] = y; g_px[b*NP + tid] = x;
    }
}

// ---------------- conv1: implicit GEMM 64x64 FFMA, K=48, gather fused -----
// Reads pred directly via patch coords; zero-pad is relative to the PATCH.
__global__ __launch_bounds__(256) void conv1_kernel(
        const float* __restrict__ pred, const float* __restrict__ w,
        const float* __restrict__ bias, __half* __restrict__ out) {
    constexpr int LOG_OW = 5, OW = 32, OHW = OW*OW, K = 48;
    __shared__ __align__(16) float As[2][16][68];
    __shared__ __align__(16) float Bs[2][16][68];
    const int tid = threadIdx.x;
    const int m0  = blockIdx.x << 6;

    const int lm = tid >> 2;
    const int kq = (tid & 3) << 2;
    const int am   = m0 + lm;
    const int p    = am >> 10;           // patch id (1024 rows per patch)
    const int b    = p >> 2;
    const int arem = am & 1023;
    const int ih0  = ((arem >> LOG_OW) << 1) - 1;
    const int iw0  = ((arem & (OW-1)) << 1) - 1;
    const int py   = g_py[p], px = g_px[p];
    const float* ibase = pred + (size_t)b*3*NPIX;

    const int boc = tid >> 2;
    const int bkq = (tid & 3) << 2;

    const int tm = (tid >> 4) << 2;
    const int tn = (tid & 15) << 2;

    float acc[4][4] = {};
    float pa[4]; float4 pbv;

    auto loadA = [&](int kc) {
        int k  = kc + kq;
        int ic = k >> 4;
        int ih = ih0 + ((k >> 2) & 3);
        bool rowok = (unsigned)ih < (unsigned)PS;
        const float* rp = ibase + ((size_t)ic*HH + py + ih)*WW + px;
        #pragma unroll
        for (int j = 0; j < 4; j++) {
            int iw = iw0 + j;
            pa[j] = (rowok && (unsigned)iw < (unsigned)PS) ? __ldg(rp + iw) : 0.f;
        }
    };
    auto loadB = [&](int kc) {
        pbv = *(const float4*)&w[(size_t)boc*K + kc + bkq];
    };
    auto stsA = [&](int buf) {
        #pragma unroll
        for (int j = 0; j < 4; j++) As[buf][kq+j][lm] = pa[j];
    };
    auto stsB = [&](int buf) {
        Bs[buf][bkq+0][boc] = pbv.x; Bs[buf][bkq+1][boc] = pbv.y;
        Bs[buf][bkq+2][boc] = pbv.z; Bs[buf][bkq+3][boc] = pbv.w;
    };

    loadA(0); loadB(0); stsA(0); stsB(0); __syncthreads();
    const int nch = K >> 4;
    for (int ch = 0; ch < nch; ch++) {
        int cur = ch & 1;
        if (ch + 1 < nch) { loadA((ch+1) << 4); loadB((ch+1) << 4); }
        #pragma unroll
        for (int k = 0; k < 16; k++) {
            float4 a = *(const float4*)&As[cur][k][tm];
            float4 bv = *(const float4*)&Bs[cur][k][tn];
            acc[0][0] += a.x*bv.x; acc[0][1] += a.x*bv.y; acc[0][2] += a.x*bv.z; acc[0][3] += a.x*bv.w;
            acc[1][0] += a.y*bv.x; acc[1][1] += a.y*bv.y; acc[1][2] += a.y*bv.z; acc[1][3] += a.y*bv.w;
            acc[2][0] += a.z*bv.x; acc[2][1] += a.z*bv.y; acc[2][2] += a.z*bv.z; acc[2][3] += a.z*bv.w;
            acc[3][0] += a.w*bv.x; acc[3][1] += a.w*bv.y; acc[3][2] += a.w*bv.z; acc[3][3] += a.w*bv.w;
        }
        if (ch + 1 < nch) { stsA(cur ^ 1); stsB(cur ^ 1); __syncthreads(); }
    }

    const float4 bv = *(const float4*)&bias[tn];
    float b4[4] = {bv.x, bv.y, bv.z, bv.w};
    #pragma unroll
    for (int i = 0; i < 4; i++) {
        int m    = m0 + tm + i;
        int ni   = m >> 10;
        int rem  = m & 1023;
        __half* op = out + ((size_t)ni*64 + tn)*OHW + rem;
        #pragma unroll
        for (int j = 0; j < 4; j++) {
            float v = acc[i][j] + b4[j];
            v = v > 0.f ? v : 0.2f*v;
            op[(size_t)j*OHW] = __float2half_rn(v);
        }
    }
}

// ---------------- fp16 mma helper ----------------
__device__ __forceinline__ void mma_fp16(float* c, const unsigned* a, const unsigned* b) {
    asm volatile(
        "mma.sync.aligned.m16n8k16.row.col.f32.f16.f16.f32 "
        "{%0,%1,%2,%3}, {%4,%5,%6,%7}, {%8,%9}, {%0,%1,%2,%3};"
        : "+f"(c[0]), "+f"(c[1]), "+f"(c[2]), "+f"(c[3])
        : "r"(a[0]), "r"(a[1]), "r"(a[2]), "r"(a[3]), "r"(b[0]), "r"(b[1]));
}

// ---------------- conv2-4: fp16 single-pass MMA, BM=64 BN=128 BK=32 ------
// BNIN: input is fp32 activations; BN+lrelu applied in loadA, fp16 in smem.
#define MSTR 40
template<int IC, int LOG_OW, bool BNIN, bool DIRECT>
__global__ __launch_bounds__(256) void conv_mma_kernel(
        const __half* __restrict__ Ah16, const float* __restrict__ Af32,
        const __half* __restrict__ Wh16,
        const float* __restrict__ bias, float* __restrict__ outd,
        float* __restrict__ part, int K, int Kchunk) {
    constexpr int OW = 1 << LOG_OW, OHW = OW*OW, IW = 2*OW, IH = IW;
    __shared__ __align__(16) uint16_t Ah[2][64][MSTR];
    __shared__ __align__(16) uint16_t Bh[2][128][MSTR];

    const int tid = threadIdx.x;
    const int m0  = blockIdx.x << 6;
    const int n0  = blockIdx.y << 7;
    const int NN  = gridDim.y << 7;
    const int MM  = gridDim.x << 6;
    const int k0  = blockIdx.z * Kchunk;
    float* pout = part + (size_t)blockIdx.z * MM * NN;

    // A mapping: row lm (0..63), k-range kq8..kq8+7
    const int lm  = tid >> 2;
    const int kq8 = (tid & 3) << 3;
    const int am   = m0 + lm;
    const int nimg = am >> (2*LOG_OW);
    const int arem = am & (OHW-1);
    const int owx  = arem & (OW-1);
    const int ih0  = ((arem >> LOG_OW) << 1) - 1;
    const int iw0  = (owx << 1) - 1;
    const bool interior = (owx >= 1) && (owx <= OW-2);
    const __half* ibh = Ah16 + (size_t)nimg*IC*IH*IW;
    const float*  ibf = Af32 + (size_t)nimg*IC*IH*IW;

    // B mapping: row brow (0..127), k-range bk16..bk16+15
    const int brow = tid >> 1;
    const int bk16 = (tid & 1) << 4;
    const __half* wrow = Wh16 + (size_t)(n0 + brow)*K;

    // warp layout: 2(m) x 4(n), warp tile 32x32
    const int wid  = tid >> 5, lane = tid & 31;
    const int wm   = (wid >> 2) << 5;
    const int wn   = (wid & 3) << 5;
    const int g    = lane >> 2;
    const int q    = lane & 3;

    float acc[2][4][4];
    #pragma unroll
    for (int i = 0; i < 2; i++)
        #pragma unroll
        for (int j = 0; j < 4; j++)
            #pragma unroll
            for (int e = 0; e < 4; e++) acc[i][j][e] = 0.f;

    unsigned paw[4]; uint4 wv[2];

    auto loadA = [&](int kc) {
        int kbase = kc + kq8;
        int ic = kbase >> 4;
        float sc = 0.f, sh = 0.f;
        if (BNIN) { sc = g_bnscale[ic]; sh = g_bnshift[ic]; }
        #pragma unroll
        for (int grp = 0; grp < 2; grp++) {
            int k  = kbase + grp*4;
            int ih = ih0 + ((k >> 2) & 3);
            bool rowok = (unsigned)ih < (unsigned)IH;
            unsigned u0 = 0u, u1 = 0u;
            if (BNIN) {
                const float* rp = ibf + ((size_t)ic*IH + ih)*IW;
                unsigned short h[4];
                #pragma unroll
                for (int j = 0; j < 4; j++) {
                    int iw = iw0 + j;
                    float v = 0.f;
                    if (rowok && (unsigned)iw < (unsigned)IW) {
                        v = __ldg(rp + iw);
                        v = v*sc + sh;
                        v = v > 0.f ? v : 0.2f*v;
                    }
                    h[j] = __half_as_ushort(__float2half_rn(v));
                }
                u0 = (unsigned)h[0] | ((unsigned)h[1] << 16);
                u1 = (unsigned)h[2] | ((unsigned)h[3] << 16);
            } else {
                const __half* rp = ibh + ((size_t)ic*IH + ih)*IW;
                if (rowok) {
                    if (interior) {
                        u0 = __ldg((const unsigned*)(rp + iw0));
                        u1 = __ldg((const unsigned*)(rp + iw0 + 2));
                    } else {
                        unsigned short h[4];
                        #pragma unroll
                        for (int j = 0; j < 4; j++) {
                            int iw = iw0 + j;
                            __half v = __ushort_as_half((unsigned short)0);
                            if ((unsigned)iw < (unsigned)IW) v = __ldg(rp + iw);
                            h[j] = __half_as_ushort(v);
                        }
                        u0 = (unsigned)h[0] | ((unsigned)h[1] << 16);
                        u1 = (unsigned)h[2] | ((unsigned)h[3] << 16);
                    }
                }
            }
            paw[grp*2]     = u0;
            paw[grp*2 + 1] = u1;
        }
    };
    auto loadB = [&](int kc) {
        wv[0] = *(const uint4*)(wrow + kc + bk16);
        wv[1] = *(const uint4*)(wrow + kc + bk16 + 8);
    };
    auto stsA = [&](int buf) {
        *(uint4*)&Ah[buf][lm][kq8] = make_uint4(paw[0], paw[1], paw[2], paw[3]);
    };
    auto stsB = [&](int buf) {
        *(uint4*)&Bh[buf][brow][bk16]     = wv[0];
        *(uint4*)&Bh[buf][brow][bk16 + 8] = wv[1];
    };

    loadA(k0); loadB(k0); stsA(0); stsB(0); __syncthreads();
    const int nch = Kchunk >> 5;
    for (int ch = 0; ch < nch; ch++) {
        int cur = ch & 1;
        if (ch + 1 < nch) { loadA(k0 + ((ch+1) << 5)); loadB(k0 + ((ch+1) << 5)); }
        #pragma unroll
        for (int step = 0; step < 2; step++) {
            const int ko = step*16 + q*2;
            unsigned ah[2][4], bh[4][2];
            #pragma unroll
            for (int mf = 0; mf < 2; mf++) {
                int r = wm + mf*16 + g;
                ah[mf][0] = *(const unsigned*)&Ah[cur][r    ][ko];
                ah[mf][1] = *(const unsigned*)&Ah[cur][r + 8][ko];
                ah[mf][2] = *(const unsigned*)&Ah[cur][r    ][ko + 8];
                ah[mf][3] = *(const unsigned*)&Ah[cur][r + 8][ko + 8];
            }
            #pragma unroll
            for (int nf = 0; nf < 4; nf++) {
                int rb = wn + nf*8 + g;
                bh[nf][0] = *(const unsigned*)&Bh[cur][rb][ko];
                bh[nf][1] = *(const unsigned*)&Bh[cur][rb][ko + 8];
            }
            #pragma unroll
            for (int mf = 0; mf < 2; mf++)
                #pragma unroll
                for (int nf = 0; nf < 4; nf++)
                    mma_fp16(acc[mf][nf], ah[mf], bh[nf]);
        }
        if (ch + 1 < nch) { stsA(cur ^ 1); stsB(cur ^ 1); __syncthreads(); }
    }

    #pragma unroll
    for (int mf = 0; mf < 2; mf++) {
        #pragma unroll
        for (int nf = 0; nf < 4; nf++) {
            int r0 = m0 + wm + mf*16 + g;
            int r1 = r0 + 8;
            int c0 = n0 + wn + nf*8 + q*2;
            if (DIRECT) {
                float bv0 = __ldg(bias + c0), bv1 = __ldg(bias + c0 + 1);
                int i0 = r0 >> (2*LOG_OW), e0 = r0 & (OHW-1);
                int i1 = r1 >> (2*LOG_OW), e1 = r1 & (OHW-1);
                float* o0 = outd + ((size_t)i0*NN + c0)*OHW + e0;
                float* o1 = outd + ((size_t)i1*NN + c0)*OHW + e1;
                o0[0]   = acc[mf][nf][0] + bv0;
                o0[OHW] = acc[mf][nf][1] + bv1;
                o1[0]   = acc[mf][nf][2] + bv0;
                o1[OHW] = acc[mf][nf][3] + bv1;
            } else {
                *(float2*)(pout + (size_t)r0*NN + c0) = make_float2(acc[mf][nf][0], acc[mf][nf][1]);
                *(float2*)(pout + (size_t)r1*NN + c0) = make_float2(acc[mf][nf][2], acc[mf][nf][3]);
            }
        }
    }
}

// ---------------- split-K reduce + bias -> NCHW ----------------
__global__ void redk_kernel(const float* __restrict__ part, const float* __restrict__ bias,
                            float* __restrict__ out, int MN, int log_nn, int KS, int log_ohw) {
    int NNm = (1 << log_nn) - 1;
    int OHWm = (1 << log_ohw) - 1;
    for (int idx = blockIdx.x*blockDim.x + threadIdx.x; idx < MN; idx += gridDim.x*blockDim.x) {
        int m = idx >> log_nn, n = idx & NNm;
        float s = 0.f;
        for (int z = 0; z < KS; z++) s += part[(size_t)z*MN + idx];
        s += bias[n];
        int ni = m >> log_ohw, rem = m & OHWm;
        out[((((size_t)ni << log_nn) + n) << log_ohw) + rem] = s;
    }
}

// ---------------- batchnorm stats (double accum) ----------------
__global__ void bn_reduce_kernel(const float* __restrict__ x, const float* __restrict__ g,
                                 const float* __restrict__ be, int N, int C, int S) {
    int c = blockIdx.x;
    double s = 0.0, s2 = 0.0;
    int M = N*S;
    for (int j = threadIdx.x; j < M; j += blockDim.x) {
        int n = j / S, sp = j % S;
        float v = x[((size_t)n*C + c)*S + sp];
        s += (double)v; s2 += (double)v*(double)v;
    }
    __shared__ double sh[256], sh2[256];
    sh[threadIdx.x] = s; sh2[threadIdx.x] = s2; __syncthreads();
    for (int st = 128; st > 0; st >>= 1) {
        if (threadIdx.x < st) { sh[threadIdx.x] += sh[threadIdx.x+st]; sh2[threadIdx.x] += sh2[threadIdx.x+st]; }
        __syncthreads();
    }
    if (threadIdx.x == 0) {
        double mean = sh[0] / M;
        double var  = sh2[0] / M - mean*mean;
        double isd  = 1.0 / sqrt(var + 1e-5);
        float sc = (float)((double)g[c] * isd);
        g_bnscale[c] = sc;
        g_bnshift[c] = be[c] - (float)(mean * (double)sc);
    }
}

// ---------------- head: bn4+lrelu+conv5 dot (64 blocks) ----------------
__global__ void head_kernel(const float* __restrict__ a4, const float* __restrict__ w5,
                            const float* __restrict__ b5) {
    int p = blockIdx.x, tid = threadIdx.x;   // 256 threads
    const float* ap = a4 + (size_t)p*8192;
    float s = 0.f;
    for (int i = tid; i < 8192; i += 256) {
        int c = i >> 4;
        float v = ap[i]*g_bnscale[c] + g_bnshift[c];
        v = v > 0.f ? v : 0.2f*v;
        s += v * w5[i];
    }
    __shared__ float sh[256];
    sh[tid] = s; __syncthreads();
    for (int st = 128; st > 0; st >>= 1) {
        if (tid < st) sh[tid] += sh[tid + st];
        __syncthreads();
    }
    if (tid == 0) g_logits[p] = sh[0] + b5[0];
}

__global__ void loss_kernel(float* __restrict__ out) {
    int tid = threadIdx.x;   // 64
    float x = -g_logits[tid];
    float sp = fmaxf(x, 0.f) + log1pf(expf(-fabsf(x)));
    __shared__ float sh[64];
    sh[tid] = sp; __syncthreads();
    for (int s = 32; s > 0; s >>= 1) { if (tid < s) sh[tid] += sh[tid+s]; __syncthreads(); }
    if (tid == 0) out[0] = sh[0] / 64.f;
}

// ---------------- launcher ----------------
extern "C" void kernel_launch(void* const* d_in, const int* in_sizes, int n_in,
                              void* d_out, int out_size) {
    const float* pred     = (const float*)d_in[0];
    const float* source   = (const float*)d_in[1];
    const int*   rand_sel = (const int*)d_in[2];
    const float* w1 = (const float*)d_in[3];  const float* b1 = (const float*)d_in[4];
    const float* w2 = (const float*)d_in[5];  const float* b2 = (const float*)d_in[6];
    const float* g2 = (const float*)d_in[7];  const float* be2= (const float*)d_in[8];
    const float* w3 = (const float*)d_in[9];  const float* b3 = (const float*)d_in[10];
    const float* g3 = (const float*)d_in[11]; const float* be3= (const float*)d_in[12];
    const float* w4 = (const float*)d_in[13]; const float* b4 = (const float*)d_in[14];
    const float* g4 = (const float*)d_in[15]; const float* be4= (const float*)d_in[16];
    const float* w5 = (const float*)d_in[17]; const float* b5 = (const float*)d_in[18];
    float* out = (float*)d_out;

    float *a2, *a3, *a4, *part;
    __half *a1h, *wh2, *wh3, *wh4;
    cudaGetSymbolAddress((void**)&a1h, g_a1h);
    cudaGetSymbolAddress((void**)&a2, g_act2);
    cudaGetSymbolAddress((void**)&a3, g_act3);
    cudaGetSymbolAddress((void**)&a4, g_act4);
    cudaGetSymbolAddress((void**)&wh2, g_wh2);
    cudaGetSymbolAddress((void**)&wh3, g_wh3);
    cudaGetSymbolAddress((void**)&wh4, g_wh4);
    cudaGetSymbolAddress((void**)&part, g_part);
    a1h += 1;   // odd half-indices become 4B-aligned

    // launches 0-2: weight converts (puts hpool at profiled index 3)
    wsplit_kernel<<<256, 256>>>(w2, wh2, 131072);
    wsplit_kernel<<<512, 256>>>(w3, wh3, 524288);
    wsplit_kernel<<<1024, 256>>>(w4, wh4, 2097152);
    // detector + pools (hist fused into vpool)
    hpool_det_kernel<<<dim3(HH, BB), 256>>>(source);
    vpool_kernel<<<dim3(WW/32, HH/64, BB), 256>>>();
    // topk: resolve threshold, collect candidates, exact rank -> coords
    topk_resolve_kernel<<<BB, 256>>>();
    topk_collect_kernel<<<dim3(48, BB), 256>>>();
    topk_final_kernel<<<BB, 1024>>>(rand_sel);
    // conv1 (gather fused: reads pred via coords; bias+lrelu; fp16 out)
    conv1_kernel<<<1024, 256>>>(pred, w1, b1, a1h);
    // conv2: M=16384, N=128, K=1024 — direct NCHW+bias
    conv_mma_kernel<64, 4, false, true><<<dim3(256, 1, 1), 256>>>(a1h, nullptr, wh2, b2, a2, nullptr, 1024, 1024);
    bn_reduce_kernel<<<128, 256>>>(a2, g2, be2, NPATCH, 128, 16*16);
    // conv3: M=4096, N=256, K=2048, split-K=4, BN2+lrelu fused into fp32 input
    conv_mma_kernel<128, 3, true, false><<<dim3(64, 2, 4), 256>>>(nullptr, a2, wh3, nullptr, nullptr, part, 2048, 512);
    redk_kernel<<<1024, 256>>>(part, b3, a3, 4096*256, 8, 4, 6);
    bn_reduce_kernel<<<256, 256>>>(a3, g3, be3, NPATCH, 256, 8*8);
    // conv4: M=1024, N=512, K=4096, split-K=8, BN3+lrelu fused into fp32 input
    conv_mma_kernel<256, 2, true, false><<<dim3(16, 4, 8), 256>>>(nullptr, a3, wh4, nullptr, nullptr, part, 4096, 512);
    redk_kernel<<<512, 256>>>(part, b4, a4, 1024*512, 9, 8, 4);
    bn_reduce_kernel<<<512, 256>>>(a4, g4, be4, NPATCH, 512, 4*4);
    // head: 64 blocks -> logits, then loss
    head_kernel<<<NPATCH, 256>>>(a4, w5, b5);
    loss_kernel<<<1, 64>>>(out);
}

// round 17
// speedup vs baseline: 1.6212x; 1.0512x over previous
#include <cuda_runtime.h>
#include <cuda_fp16.h>
#include <cstdint>
#include <math.h>

#define BB 16
#define HH 768
#define WW 768
#define NPIX (HH*WW)
#define TOPK 100
#define NP 4
#define NPATCH (BB*NP)   // 64
#define PS 64            // patch size
#define CANDCAP 16384

// ---------------- scratch (static device globals) ----------------
__device__ float g_mask[BB*NPIX];
__device__ float g_tmp[BB*NPIX];
__device__ unsigned g_hist12[BB][4096];
__device__ unsigned g_T12[BB];
__device__ int g_candn[BB];
__device__ unsigned long long g_cand[BB][CANDCAP];
__device__ int g_py[NPATCH], g_px[NPATCH];
// +8 halfs pad; kernels use base+1 so odd half-indices are 4B-aligned
__device__ __align__(16) __half g_a1h[NPATCH*64*32*32 + 8];
__device__ float g_act2[NPATCH*128*16*16];
__device__ float g_act3[NPATCH*256*8*8];
__device__ float g_act4[NPATCH*512*4*4];
__device__ __half g_wh2[128*1024];
__device__ __half g_wh3[256*2048];
__device__ __half g_wh4[512*4096];
__device__ float g_part[4194304];
__device__ float g_bnscale[512], g_bnshift[512];
__device__ float g_logits[NPATCH];

// ---------------- weight convert: fp32 -> fp16 (3 small launches) --------
__global__ void wsplit_kernel(const float* __restrict__ w, __half* __restrict__ o, int n) {
    for (int i = blockIdx.x*blockDim.x + threadIdx.x; i < n; i += gridDim.x*blockDim.x)
        o[i] = __float2half_rn(w[i]);
}

// ---------------- detector fused into 15-tap horizontal pool ---------------
// running-sum: each thread produces 3 consecutive outputs
__global__ void hpool_det_kernel(const float* __restrict__ src) {
    if (blockIdx.y == 0 && blockIdx.x < 64) {
        int base = blockIdx.x * 1024;
        for (int i = threadIdx.x; i < 1024; i += 256)
            ((unsigned*)g_hist12)[base + i] = 0u;
    }
    if (blockIdx.y == 0 && blockIdx.x == 100 && threadIdx.x < BB)
        g_candn[threadIdx.x] = 0;

    __shared__ float row[WW + 14];
    int y = blockIdx.x, b = blockIdx.y;
    const float* sb = src + ((size_t)b*3*HH + y)*WW;
    for (int i = threadIdx.x; i < WW + 14; i += blockDim.x) {
        int x = i - 7;
        float m = 0.f;
        if (x >= 0 && x < WW) {
            float r  = (sb[x]               + 1.f)*0.5f;
            float gg = (sb[(size_t)HH*WW + x]   + 1.f)*0.5f;
            float bl = (sb[(size_t)2*HH*WW + x] + 1.f)*0.5f;
            float br = 0.299f*r + 0.587f*gg + 0.114f*bl;
            float bm = 1.f/(1.f + expf(-20.f*(br - 0.65f)));
            float mx = fmaxf(r, fmaxf(gg, bl));
            float mn = fminf(r, fminf(gg, bl));
            float ls = 1.f/(1.f + expf(-20.f*(0.15f - (mx - mn))));
            m = bm*ls;
        }
        row[i] = m;
    }
    __syncthreads();
    float* op = g_tmp + ((size_t)b*HH + y)*WW;
    int x0 = 3*threadIdx.x;                 // 256 threads x 3 = 768
    float s = 0.f;
    #pragma unroll
    for (int d = 0; d < 15; d++) s += row[x0 + d];
    op[x0] = s;
    #pragma unroll
    for (int j = 1; j < 3; j++) {
        s += row[x0 + 14 + j] - row[x0 + j - 1];
        op[x0 + j] = s;
    }
}

// ---------------- 15-tap vertical running-sum + /225 -> g_mask + hist -----
// 256 threads = 32 cols x 8 row-groups; each thread: 8 consecutive rows
__global__ void vpool_kernel() {
    __shared__ float tile[78][32];
    __shared__ unsigned shist[4096];
    int c0 = blockIdx.x*32, r0 = blockIdx.y*64, b = blockIdx.z;
    for (int i = threadIdx.x; i < 4096; i += blockDim.x) shist[i] = 0u;
    const float* ip = g_tmp + (size_t)b*NPIX;
    for (int i = threadIdx.x; i < 78*32; i += blockDim.x) {
        int r = i >> 5, c = i & 31;
        int y = r0 + r - 7;
        tile[r][c] = (y >= 0 && y < HH) ? ip[(size_t)y*WW + c0 + c] : 0.f;
    }
    __syncthreads();
    float* op = g_mask + (size_t)b*NPIX;
    int c = threadIdx.x & 31;
    int gr = threadIdx.x >> 5;              // 0..7
    int rb = gr*8;
    float s = 0.f;
    #pragma unroll
    for (int d = 0; d < 15; d++) s += tile[rb + d][c];
    {
        float v = s / 225.0f;
        op[(size_t)(r0 + rb)*WW + c0 + c] = v;
        atomicAdd(&shist[__float_as_uint(v) >> 20], 1u);
    }
    #pragma unroll
    for (int j = 1; j < 8; j++) {
        s += tile[rb + 14 + j][c] - tile[rb + j - 1][c];
        float v = s / 225.0f;
        op[(size_t)(r0 + rb + j)*WW + c0 + c] = v;
        atomicAdd(&shist[__float_as_uint(v) >> 20], 1u);
    }
    __syncthreads();
    for (int i = threadIdx.x; i < 4096; i += blockDim.x) {
        unsigned cc = shist[i];
        if (cc) atomicAdd(&g_hist12[b][i], cc);
    }
}

// ---------------- resolve 12-bit threshold ----------------
__global__ void topk_resolve_kernel() {
    int b = blockIdx.x, t = threadIdx.x;   // 256 threads
    __shared__ unsigned csum[257];
    __shared__ int s_c;
    unsigned s = 0;
    #pragma unroll
    for (int j = 0; j < 16; j++) s += g_hist12[b][t*16 + j];
    csum[t] = s;
    if (t == 0) csum[256] = 0;
    __syncthreads();
    for (int off = 1; off < 256; off <<= 1) {
        unsigned v = csum[t] + ((t + off < 256) ? csum[t + off] : 0u);
        __syncthreads();
        csum[t] = v;
        __syncthreads();
    }
    if (csum[t] >= TOPK && (t == 255 || csum[t + 1] < TOPK)) s_c = t;
    __syncthreads();
    if (t == 0) {
        int cch = s_c;
        unsigned running = (cch == 255) ? 0u : csum[cch + 1];
        unsigned T = (unsigned)(cch*16);
        for (int bin = cch*16 + 15; bin >= cch*16; bin--) {
            running += g_hist12[b][bin];
            if (running >= TOPK) { T = (unsigned)bin; break; }
        }
        g_T12[b] = T;
    }
}

// ---------------- collect candidates (one full scan, grid-wide) ----------
__global__ void topk_collect_kernel() {
    int b = blockIdx.y;
    unsigned T = g_T12[b];
    const float4* wp4 = (const float4*)(g_mask + (size_t)b*NPIX);
    for (int i = blockIdx.x*blockDim.x + threadIdx.x; i < NPIX/4; i += gridDim.x*blockDim.x) {
        float4 v = wp4[i];
        unsigned kk[4] = {__float_as_uint(v.x), __float_as_uint(v.y),
                          __float_as_uint(v.z), __float_as_uint(v.w)};
        #pragma unroll
        for (int j = 0; j < 4; j++) {
            if ((kk[j] >> 20) >= T) {
                int p = atomicAdd(&g_candn[b], 1);
                if (p < CANDCAP)
                    g_cand[b][p] = ((unsigned long long)kk[j] << 32)
                                 | (unsigned)(0xFFFFFFFFu - (unsigned)(4*i + j));
            }
        }
    }
}

// ---------------- exact top-100 by rank + coords ----------------
__global__ __launch_bounds__(1024) void topk_final_kernel(const int* __restrict__ rand_sel) {
    int b = blockIdx.x, tid = threadIdx.x;
    __shared__ unsigned long long ch[2048];
    __shared__ int stop[TOPK];
    int n = min(g_candn[b], CANDCAP);
    unsigned long long vi[16]; int ri[16]; int nc = 0;
    for (int i = tid; i < n; i += 1024) {
        if (nc < 16) { vi[nc] = g_cand[b][i]; ri[nc] = 0; nc++; }
    }
    for (int base = 0; base < n; base += 2048) {
        int len = min(2048, n - base);
        for (int j = tid; j < len; j += 1024) ch[j] = g_cand[b][base + j];
        __syncthreads();
        for (int cnd = 0; cnd < nc; cnd++) {
            unsigned long long v = vi[cnd]; int r = 0;
            for (int j = 0; j < len; j++) r += (ch[j] > v) ? 1 : 0;
            ri[cnd] += r;
        }
        __syncthreads();
    }
    for (int cnd = 0; cnd < nc; cnd++)
        if (ri[cnd] < TOPK)
            stop[ri[cnd]] = (int)(0xFFFFFFFFu - (unsigned)(vi[cnd] & 0xFFFFFFFFu));
    __syncthreads();
    if (tid < NP) {
        int r = rand_sel[b*NP + tid];
        int sel = stop[r];
        int y = sel / WW - PS/2; y = max(0, min(y, HH - PS));
        int x = sel % WW - PS/2; x = max(0, min(x, WW - PS));
        g_py[b*NP + tid] = y; g_px[b*NP + tid] = x;
    }
}

// ---------------- conv1: implicit GEMM 64x64 FFMA, K=48, gather fused -----
__global__ __launch_bounds__(256) void conv1_kernel(
        const float* __restrict__ pred, const float* __restrict__ w,
        const float* __restrict__ bias, __half* __restrict__ out) {
    constexpr int LOG_OW = 5, OW = 32, OHW = OW*OW, K = 48;
    __shared__ __align__(16) float As[2][16][68];
    __shared__ __align__(16) float Bs[2][16][68];
    const int tid = threadIdx.x;
    const int m0  = blockIdx.x << 6;

    const int lm = tid >> 2;
    const int kq = (tid & 3) << 2;
    const int am   = m0 + lm;
    const int p    = am >> 10;
    const int b    = p >> 2;
    const int arem = am & 1023;
    const int ih0  = ((arem >> LOG_OW) << 1) - 1;
    const int iw0  = ((arem & (OW-1)) << 1) - 1;
    const int py   = g_py[p], px = g_px[p];
    const float* ibase = pred + (size_t)b*3*NPIX;

    const int boc = tid >> 2;
    const int bkq = (tid & 3) << 2;

    const int tm = (tid >> 4) << 2;
    const int tn = (tid & 15) << 2;

    float acc[4][4] = {};
    float pa[4]; float4 pbv;

    auto loadA = [&](int kc) {
        int k  = kc + kq;
        int ic = k >> 4;
        int ih = ih0 + ((k >> 2) & 3);
        bool rowok = (unsigned)ih < (unsigned)PS;
        const float* rp = ibase + ((size_t)ic*HH + py + ih)*WW + px;
        #pragma unroll
        for (int j = 0; j < 4; j++) {
            int iw = iw0 + j;
            pa[j] = (rowok && (unsigned)iw < (unsigned)PS) ? __ldg(rp + iw) : 0.f;
        }
    };
    auto loadB = [&](int kc) {
        pbv = *(const float4*)&w[(size_t)boc*K + kc + bkq];
    };
    auto stsA = [&](int buf) {
        #pragma unroll
        for (int j = 0; j < 4; j++) As[buf][kq+j][lm] = pa[j];
    };
    auto stsB = [&](int buf) {
        Bs[buf][bkq+0][boc] = pbv.x; Bs[buf][bkq+1][boc] = pbv.y;
        Bs[buf][bkq+2][boc] = pbv.z; Bs[buf][bkq+3][boc] = pbv.w;
    };

    loadA(0); loadB(0); stsA(0); stsB(0); __syncthreads();
    const int nch = K >> 4;
    for (int ch = 0; ch < nch; ch++) {
        int cur = ch & 1;
        if (ch + 1 < nch) { loadA((ch+1) << 4); loadB((ch+1) << 4); }
        #pragma unroll
        for (int k = 0; k < 16; k++) {
            float4 a = *(const float4*)&As[cur][k][tm];
            float4 bv = *(const float4*)&Bs[cur][k][tn];
            acc[0][0] += a.x*bv.x; acc[0][1] += a.x*bv.y; acc[0][2] += a.x*bv.z; acc[0][3] += a.x*bv.w;
            acc[1][0] += a.y*bv.x; acc[1][1] += a.y*bv.y; acc[1][2] += a.y*bv.z; acc[1][3] += a.y*bv.w;
            acc[2][0] += a.z*bv.x; acc[2][1] += a.z*bv.y; acc[2][2] += a.z*bv.z; acc[2][3] += a.z*bv.w;
            acc[3][0] += a.w*bv.x; acc[3][1] += a.w*bv.y; acc[3][2] += a.w*bv.z; acc[3][3] += a.w*bv.w;
        }
        if (ch + 1 < nch) { stsA(cur ^ 1); stsB(cur ^ 1); __syncthreads(); }
    }

    const float4 bv = *(const float4*)&bias[tn];
    float b4[4] = {bv.x, bv.y, bv.z, bv.w};
    #pragma unroll
    for (int i = 0; i < 4; i++) {
        int m    = m0 + tm + i;
        int ni   = m >> 10;
        int rem  = m & 1023;
        __half* op = out + ((size_t)ni*64 + tn)*OHW + rem;
        #pragma unroll
        for (int j = 0; j < 4; j++) {
            float v = acc[i][j] + b4[j];
            v = v > 0.f ? v : 0.2f*v;
            op[(size_t)j*OHW] = __float2half_rn(v);
        }
    }
}

// ---------------- fp16 mma helper ----------------
__device__ __forceinline__ void mma_fp16(float* c, const unsigned* a, const unsigned* b) {
    asm volatile(
        "mma.sync.aligned.m16n8k16.row.col.f32.f16.f16.f32 "
        "{%0,%1,%2,%3}, {%4,%5,%6,%7}, {%8,%9}, {%0,%1,%2,%3};"
        : "+f"(c[0]), "+f"(c[1]), "+f"(c[2]), "+f"(c[3])
        : "r"(a[0]), "r"(a[1]), "r"(a[2]), "r"(a[3]), "r"(b[0]), "r"(b[1]));
}

// ---------------- conv2-4: fp16 single-pass MMA, BM=64 BN=128 BK=32 ------
#define MSTR 40
template<int IC, int LOG_OW, bool BNIN, bool DIRECT>
__global__ __launch_bounds__(256) void conv_mma_kernel(
        const __half* __restrict__ Ah16, const float* __restrict__ Af32,
        const __half* __restrict__ Wh16,
        const float* __restrict__ bias, float* __restrict__ outd,
        float* __restrict__ part, int K, int Kchunk) {
    constexpr int OW = 1 << LOG_OW, OHW = OW*OW, IW = 2*OW, IH = IW;
    __shared__ __align__(16) uint16_t Ah[2][64][MSTR];
    __shared__ __align__(16) uint16_t Bh[2][128][MSTR];

    const int tid = threadIdx.x;
    const int m0  = blockIdx.x << 6;
    const int n0  = blockIdx.y << 7;
    const int NN  = gridDim.y << 7;
    const int MM  = gridDim.x << 6;
    const int k0  = blockIdx.z * Kchunk;
    float* pout = part + (size_t)blockIdx.z * MM * NN;

    const int lm  = tid >> 2;
    const int kq8 = (tid & 3) << 3;
    const int am   = m0 + lm;
    const int nimg = am >> (2*LOG_OW);
    const int arem = am & (OHW-1);
    const int owx  = arem & (OW-1);
    const int ih0  = ((arem >> LOG_OW) << 1) - 1;
    const int iw0  = (owx << 1) - 1;
    const bool interior = (owx >= 1) && (owx <= OW-2);
    const __half* ibh = Ah16 + (size_t)nimg*IC*IH*IW;
    const float*  ibf = Af32 + (size_t)nimg*IC*IH*IW;

    const int brow = tid >> 1;
    const int bk16 = (tid & 1) << 4;
    const __half* wrow = Wh16 + (size_t)(n0 + brow)*K;

    const int wid  = tid >> 5, lane = tid & 31;
    const int wm   = (wid >> 2) << 5;
    const int wn   = (wid & 3) << 5;
    const int g    = lane >> 2;
    const int q    = lane & 3;

    float acc[2][4][4];
    #pragma unroll
    for (int i = 0; i < 2; i++)
        #pragma unroll
        for (int j = 0; j < 4; j++)
            #pragma unroll
            for (int e = 0; e < 4; e++) acc[i][j][e] = 0.f;

    unsigned paw[4]; uint4 wv[2];

    auto loadA = [&](int kc) {
        int kbase = kc + kq8;
        int ic = kbase >> 4;
        float sc = 0.f, sh = 0.f;
        if (BNIN) { sc = g_bnscale[ic]; sh = g_bnshift[ic]; }
        #pragma unroll
        for (int grp = 0; grp < 2; grp++) {
            int k  = kbase + grp*4;
            int ih = ih0 + ((k >> 2) & 3);
            bool rowok = (unsigned)ih < (unsigned)IH;
            unsigned u0 = 0u, u1 = 0u;
            if (BNIN) {
                const float* rp = ibf + ((size_t)ic*IH + ih)*IW;
                unsigned short h[4];
                #pragma unroll
                for (int j = 0; j < 4; j++) {
                    int iw = iw0 + j;
                    float v = 0.f;
                    if (rowok && (unsigned)iw < (unsigned)IW) {
                        v = __ldg(rp + iw);
                        v = v*sc + sh;
                        v = v > 0.f ? v : 0.2f*v;
                    }
                    h[j] = __half_as_ushort(__float2half_rn(v));
                }
                u0 = (unsigned)h[0] | ((unsigned)h[1] << 16);
                u1 = (unsigned)h[2] | ((unsigned)h[3] << 16);
            } else {
                const __half* rp = ibh + ((size_t)ic*IH + ih)*IW;
                if (rowok) {
                    if (interior) {
                        u0 = __ldg((const unsigned*)(rp + iw0));
                        u1 = __ldg((const unsigned*)(rp + iw0 + 2));
                    } else {
                        unsigned short h[4];
                        #pragma unroll
                        for (int j = 0; j < 4; j++) {
                            int iw = iw0 + j;
                            __half v = __ushort_as_half((unsigned short)0);
                            if ((unsigned)iw < (unsigned)IW) v = __ldg(rp + iw);
                            h[j] = __half_as_ushort(v);
                        }
                        u0 = (unsigned)h[0] | ((unsigned)h[1] << 16);
                        u1 = (unsigned)h[2] | ((unsigned)h[3] << 16);
                    }
                }
            }
            paw[grp*2]     = u0;
            paw[grp*2 + 1] = u1;
        }
    };
    auto loadB = [&](int kc) {
        wv[0] = *(const uint4*)(wrow + kc + bk16);
        wv[1] = *(const uint4*)(wrow + kc + bk16 + 8);
    };
    auto stsA = [&](int buf) {
        *(uint4*)&Ah[buf][lm][kq8] = make_uint4(paw[0], paw[1], paw[2], paw[3]);
    };
    auto stsB = [&](int buf) {
        *(uint4*)&Bh[buf][brow][bk16]     = wv[0];
        *(uint4*)&Bh[buf][brow][bk16 + 8] = wv[1];
    };

    loadA(k0); loadB(k0); stsA(0); stsB(0); __syncthreads();
    const int nch = Kchunk >> 5;
    for (int ch = 0; ch < nch; ch++) {
        int cur = ch & 1;
        if (ch + 1 < nch) { loadA(k0 + ((ch+1) << 5)); loadB(k0 + ((ch+1) << 5)); }
        #pragma unroll
        for (int step = 0; step < 2; step++) {
            const int ko = step*16 + q*2;
            unsigned ah[2][4], bh[4][2];
            #pragma unroll
            for (int mf = 0; mf < 2; mf++) {
                int r = wm + mf*16 + g;
                ah[mf][0] = *(const unsigned*)&Ah[cur][r    ][ko];
                ah[mf][1] = *(const unsigned*)&Ah[cur][r + 8][ko];
                ah[mf][2] = *(const unsigned*)&Ah[cur][r    ][ko + 8];
                ah[mf][3] = *(const unsigned*)&Ah[cur][r + 8][ko + 8];
            }
            #pragma unroll
            for (int nf = 0; nf < 4; nf++) {
                int rb = wn + nf*8 + g;
                bh[nf][0] = *(const unsigned*)&Bh[cur][rb][ko];
                bh[nf][1] = *(const unsigned*)&Bh[cur][rb][ko + 8];
            }
            #pragma unroll
            for (int mf = 0; mf < 2; mf++)
                #pragma unroll
                for (int nf = 0; nf < 4; nf++)
                    mma_fp16(acc[mf][nf], ah[mf], bh[nf]);
        }
        if (ch + 1 < nch) { stsA(cur ^ 1); stsB(cur ^ 1); __syncthreads(); }
    }

    #pragma unroll
    for (int mf = 0; mf < 2; mf++) {
        #pragma unroll
        for (int nf = 0; nf < 4; nf++) {
            int r0 = m0 + wm + mf*16 + g;
            int r1 = r0 + 8;
            int c0 = n0 + wn + nf*8 + q*2;
            if (DIRECT) {
                float bv0 = __ldg(bias + c0), bv1 = __ldg(bias + c0 + 1);
                int i0 = r0 >> (2*LOG_OW), e0 = r0 & (OHW-1);
                int i1 = r1 >> (2*LOG_OW), e1 = r1 & (OHW-1);
                float* o0 = outd + ((size_t)i0*NN + c0)*OHW + e0;
                float* o1 = outd + ((size_t)i1*NN + c0)*OHW + e1;
                o0[0]   = acc[mf][nf][0] + bv0;
                o0[OHW] = acc[mf][nf][1] + bv1;
                o1[0]   = acc[mf][nf][2] + bv0;
                o1[OHW] = acc[mf][nf][3] + bv1;
            } else {
                *(float2*)(pout + (size_t)r0*NN + c0) = make_float2(acc[mf][nf][0], acc[mf][nf][1]);
                *(float2*)(pout + (size_t)r1*NN + c0) = make_float2(acc[mf][nf][2], acc[mf][nf][3]);
            }
        }
    }
}

// ---------------- split-K reduce + bias -> NCHW ----------------
__global__ void redk_kernel(const float* __restrict__ part, const float* __restrict__ bias,
                            float* __restrict__ out, int MN, int log_nn, int KS, int log_ohw) {
    int NNm = (1 << log_nn) - 1;
    int OHWm = (1 << log_ohw) - 1;
    for (int idx = blockIdx.x*blockDim.x + threadIdx.x; idx < MN; idx += gridDim.x*blockDim.x) {
        int m = idx >> log_nn, n = idx & NNm;
        float s = 0.f;
        for (int z = 0; z < KS; z++) s += part[(size_t)z*MN + idx];
        s += bias[n];
        int ni = m >> log_ohw, rem = m & OHWm;
        out[((((size_t)ni << log_nn) + n) << log_ohw) + rem] = s;
    }
}

// ---------------- batchnorm stats (double accum) ----------------
__global__ void bn_reduce_kernel(const float* __restrict__ x, const float* __restrict__ g,
                                 const float* __restrict__ be, int N, int C, int S) {
    int c = blockIdx.x;
    double s = 0.0, s2 = 0.0;
    int M = N*S;
    for (int j = threadIdx.x; j < M; j += blockDim.x) {
        int n = j / S, sp = j % S;
        float v = x[((size_t)n*C + c)*S + sp];
        s += (double)v; s2 += (double)v*(double)v;
    }
    __shared__ double sh[256], sh2[256];
    sh[threadIdx.x] = s; sh2[threadIdx.x] = s2; __syncthreads();
    for (int st = 128; st > 0; st >>= 1) {
        if (threadIdx.x < st) { sh[threadIdx.x] += sh[threadIdx.x+st]; sh2[threadIdx.x] += sh2[threadIdx.x+st]; }
        __syncthreads();
    }
    if (threadIdx.x == 0) {
        double mean = sh[0] / M;
        double var  = sh2[0] / M - mean*mean;
        double isd  = 1.0 / sqrt(var + 1e-5);
        float sc = (float)((double)g[c] * isd);
        g_bnscale[c] = sc;
        g_bnshift[c] = be[c] - (float)(mean * (double)sc);
    }
}

// ---------------- head: bn4+lrelu+conv5 dot (64 blocks) ----------------
__global__ void head_kernel(const float* __restrict__ a4, const float* __restrict__ w5,
                            const float* __restrict__ b5) {
    int p = blockIdx.x, tid = threadIdx.x;   // 256 threads
    const float* ap = a4 + (size_t)p*8192;
    float s = 0.f;
    for (int i = tid; i < 8192; i += 256) {
        int c = i >> 4;
        float v = ap[i]*g_bnscale[c] + g_bnshift[c];
        v = v > 0.f ? v : 0.2f*v;
        s += v * w5[i];
    }
    __shared__ float sh[256];
    sh[tid] = s; __syncthreads();
    for (int st = 128; st > 0; st >>= 1) {
        if (tid < st) sh[tid] += sh[tid + st];
        __syncthreads();
    }
    if (tid == 0) g_logits[p] = sh[0] + b5[0];
}

__global__ void loss_kernel(float* __restrict__ out) {
    int tid = threadIdx.x;   // 64
    float x = -g_logits[tid];
    float sp = fmaxf(x, 0.f) + log1pf(expf(-fabsf(x)));
    __shared__ float sh[64];
    sh[tid] = sp; __syncthreads();
    for (int s = 32; s > 0; s >>= 1) { if (tid < s) sh[tid] += sh[tid+s]; __syncthreads(); }
    if (tid == 0) out[0] = sh[0] / 64.f;
}

// ---------------- launcher ----------------
extern "C" void kernel_launch(void* const* d_in, const int* in_sizes, int n_in,
                              void* d_out, int out_size) {
    const float* pred     = (const float*)d_in[0];
    const float* source   = (const float*)d_in[1];
    const int*   rand_sel = (const int*)d_in[2];
    const float* w1 = (const float*)d_in[3];  const float* b1 = (const float*)d_in[4];
    const float* w2 = (const float*)d_in[5];  const float* b2 = (const float*)d_in[6];
    const float* g2 = (const float*)d_in[7];  const float* be2= (const float*)d_in[8];
    const float* w3 = (const float*)d_in[9];  const float* b3 = (const float*)d_in[10];
    const float* g3 = (const float*)d_in[11]; const float* be3= (const float*)d_in[12];
    const float* w4 = (const float*)d_in[13]; const float* b4 = (const float*)d_in[14];
    const float* g4 = (const float*)d_in[15]; const float* be4= (const float*)d_in[16];
    const float* w5 = (const float*)d_in[17]; const float* b5 = (const float*)d_in[18];
    float* out = (float*)d_out;

    float *a2, *a3, *a4, *part;
    __half *a1h, *wh2, *wh3, *wh4;
    cudaGetSymbolAddress((void**)&a1h, g_a1h);
    cudaGetSymbolAddress((void**)&a2, g_act2);
    cudaGetSymbolAddress((void**)&a3, g_act3);
    cudaGetSymbolAddress((void**)&a4, g_act4);
    cudaGetSymbolAddress((void**)&wh2, g_wh2);
    cudaGetSymbolAddress((void**)&wh3, g_wh3);
    cudaGetSymbolAddress((void**)&wh4, g_wh4);
    cudaGetSymbolAddress((void**)&part, g_part);
    a1h += 1;   // odd half-indices become 4B-aligned

    // launches 0-2: weight converts
    wsplit_kernel<<<256, 256>>>(w2, wh2, 131072);
    wsplit_kernel<<<512, 256>>>(w3, wh3, 524288);
    wsplit_kernel<<<1024, 256>>>(w4, wh4, 2097152);
    // detector + pools (hist fused into vpool)
    hpool_det_kernel<<<dim3(HH, BB), 256>>>(source);
    vpool_kernel<<<dim3(WW/32, HH/64, BB), 256>>>();
    // topk: resolve threshold, collect candidates, exact rank -> coords
    topk_resolve_kernel<<<BB, 256>>>();
    topk_collect_kernel<<<dim3(48, BB), 256>>>();
    topk_final_kernel<<<BB, 1024>>>(rand_sel);
    // conv1 (gather fused: reads pred via coords; bias+lrelu; fp16 out)
    conv1_kernel<<<1024, 256>>>(pred, w1, b1, a1h);
    // conv2: M=16384, N=128, K=1024 — direct NCHW+bias
    conv_mma_kernel<64, 4, false, true><<<dim3(256, 1, 1), 256>>>(a1h, nullptr, wh2, b2, a2, nullptr, 1024, 1024);
    bn_reduce_kernel<<<128, 256>>>(a2, g2, be2, NPATCH, 128, 16*16);
    // conv3: M=4096, N=256, K=2048, split-K=2, BN2+lrelu fused into fp32 input
    conv_mma_kernel<128, 3, true, false><<<dim3(64, 2, 2), 256>>>(nullptr, a2, wh3, nullptr, nullptr, part, 2048, 1024);
    redk_kernel<<<1024, 256>>>(part, b3, a3, 4096*256, 8, 2, 6);
    bn_reduce_kernel<<<256, 256>>>(a3, g3, be3, NPATCH, 256, 8*8);
    // conv4: M=1024, N=512, K=4096, split-K=4, BN3+lrelu fused into fp32 input
    conv_mma_kernel<256, 2, true, false><<<dim3(16, 4, 4), 256>>>(nullptr, a3, wh4, nullptr, nullptr, part, 4096, 1024);
    redk_kernel<<<512, 256>>>(part, b4, a4, 1024*512, 9, 4, 4);
    bn_reduce_kernel<<<512, 256>>>(a4, g4, be4, NPATCH, 512, 4*4);
    // head: 64 blocks -> logits, then loss
    head_kernel<<<NPATCH, 256>>>(a4, w5, b5);
    loss_kernel<<<1, 64>>>(out);
}